// round 1
// baseline (speedup 1.0000x reference)
#include <cuda_runtime.h>
#include <math.h>

#define T_  2048
#define B_  2
#define D_  1024
#define H_  16
#define HD  64
#define ROWS (T_*B_)   // 4096
#define BH  (B_*H_)    // 32
#define SCALING 0.125f // 1/sqrt(64)

// Scratch (device globals — allocation-free kernel_launch)
__device__ float g_qh[BH * T_ * HD];   // [b,h,t,d]
__device__ float g_kh[BH * T_ * HD];
__device__ float g_vh[BH * T_ * HD];
__device__ float g_attn[ROWS * D_];    // [t,b, h*64+d]
__device__ float g_lse[BH * T_];

// ---------------------------------------------------------------------------
// Kernel 1: fused Q/K/V projections.  C = X @ W^T + bias (Q also scaled).
// X: [4096,1024] row-major (row r = t*B+b). W: [1024,1024] row-major [out,in].
// Output written head-split: g_?h[((b*H+h)*T + t)*64 + d].
// Tiling: 64x64 output tile, BK=16, 256 threads, 4x4 per thread.
// ---------------------------------------------------------------------------
__global__ void proj_kernel(const float* __restrict__ x,
                            const float* __restrict__ qw, const float* __restrict__ qb,
                            const float* __restrict__ kw, const float* __restrict__ kb,
                            const float* __restrict__ vw, const float* __restrict__ vb)
{
    __shared__ float As[64][17];
    __shared__ float Bs[64][17];

    int which = blockIdx.z;
    const float* w    = (which == 0) ? qw : (which == 1) ? kw : vw;
    const float* bias = (which == 0) ? qb : (which == 1) ? kb : vb;
    float* outp       = (which == 0) ? g_qh : (which == 1) ? g_kh : g_vh;

    int r0 = blockIdx.y * 64;
    int c0 = blockIdx.x * 64;
    int tx = threadIdx.x, ty = threadIdx.y;
    int tid = ty * 16 + tx;

    float acc[4][4] = {};

    for (int k0 = 0; k0 < D_; k0 += 16) {
        #pragma unroll
        for (int i = 0; i < 4; i++) {
            int idx = tid + i * 256;
            int row = idx >> 4, kk = idx & 15;
            As[row][kk] = x[(size_t)(r0 + row) * D_ + k0 + kk];
            Bs[row][kk] = w[(size_t)(c0 + row) * D_ + k0 + kk];
        }
        __syncthreads();
        #pragma unroll
        for (int kk = 0; kk < 16; kk++) {
            float a[4], b[4];
            #pragma unroll
            for (int i = 0; i < 4; i++) a[i] = As[ty * 4 + i][kk];
            #pragma unroll
            for (int j = 0; j < 4; j++) b[j] = Bs[tx * 4 + j][kk];
            #pragma unroll
            for (int i = 0; i < 4; i++)
                #pragma unroll
                for (int j = 0; j < 4; j++) acc[i][j] += a[i] * b[j];
        }
        __syncthreads();
    }

    #pragma unroll
    for (int i = 0; i < 4; i++) {
        int r = r0 + ty * 4 + i;
        int t = r >> 1, b = r & 1;   // r = t*B + b, B=2
        #pragma unroll
        for (int j = 0; j < 4; j++) {
            int o = c0 + tx * 4 + j;
            float v = acc[i][j] + bias[o];
            if (which == 0) v *= SCALING;
            int h = o >> 6, d = o & 63;
            outp[((size_t)(b * H_ + h) * T_ + t) * HD + d] = v;
        }
    }
}

// ---------------------------------------------------------------------------
// Kernel 2: causal flash attention per (b,h, 64-row q-tile).
// Online softmax; writes attn [T,B,D] layout + lse per row.
// Dynamic smem: Qs[64][65] | KVs[64][65] | Ps[64][65]  (49,920 B)
// ---------------------------------------------------------------------------
extern __shared__ float fa_sm[];
__global__ void flash_kernel()
{
    float* Qs  = fa_sm;            // [64][65]
    float* KVs = fa_sm + 64 * 65;  // [64][65] (K then reused for V)
    float* Ps  = fa_sm + 2 * 64 * 65;
    __shared__ float mrow[64], lrow[64], srow[64];

    int bh = blockIdx.y;
    int t0 = blockIdx.x * 64;
    int tx = threadIdx.x, ty = threadIdx.y;
    int tid = ty * 16 + tx;

    const float* qbase = g_qh + (size_t)bh * T_ * HD;
    const float* kbase = g_kh + (size_t)bh * T_ * HD;
    const float* vbase = g_vh + (size_t)bh * T_ * HD;

    for (int i = tid; i < 64 * 64; i += 256) {
        int row = i >> 6, d = i & 63;
        Qs[row * 65 + d] = qbase[(size_t)(t0 + row) * HD + d];
    }
    if (tid < 64) { mrow[tid] = -1e30f; lrow[tid] = 0.0f; }
    float o4[4][4] = {};
    __syncthreads();

    int nst = blockIdx.x + 1;          // causal: s-tiles 0..t_tile
    for (int st = 0; st < nst; st++) {
        int s0 = st * 64;
        for (int i = tid; i < 64 * 64; i += 256) {
            int row = i >> 6, d = i & 63;
            KVs[row * 65 + d] = kbase[(size_t)(s0 + row) * HD + d];
        }
        __syncthreads();

        float s4[4][4] = {};
        #pragma unroll 8
        for (int d = 0; d < 64; d++) {
            float a[4], b[4];
            #pragma unroll
            for (int i = 0; i < 4; i++) a[i] = Qs[(ty * 4 + i) * 65 + d];
            #pragma unroll
            for (int j = 0; j < 4; j++) b[j] = KVs[(tx * 4 + j) * 65 + d];
            #pragma unroll
            for (int i = 0; i < 4; i++)
                #pragma unroll
                for (int j = 0; j < 4; j++) s4[i][j] += a[i] * b[j];
        }
        #pragma unroll
        for (int i = 0; i < 4; i++) {
            int tg = t0 + ty * 4 + i;
            #pragma unroll
            for (int j = 0; j < 4; j++) {
                int sg = s0 + tx * 4 + j;
                Ps[(ty * 4 + i) * 65 + tx * 4 + j] = (sg <= tg) ? s4[i][j] : -1e30f;
            }
        }
        __syncthreads();

        if (tid < 64) {
            float mold = mrow[tid];
            float mx = mold;
            float* p = Ps + tid * 65;
            #pragma unroll 8
            for (int c = 0; c < 64; c++) mx = fmaxf(mx, p[c]);
            float fac = expf(mold - mx);
            float l = lrow[tid] * fac;
            #pragma unroll 4
            for (int c = 0; c < 64; c++) { float e = expf(p[c] - mx); p[c] = e; l += e; }
            mrow[tid] = mx; lrow[tid] = l; srow[tid] = fac;
        }
        __syncthreads();

        for (int i = tid; i < 64 * 64; i += 256) {
            int row = i >> 6, d = i & 63;
            KVs[row * 65 + d] = vbase[(size_t)(s0 + row) * HD + d];
        }
        __syncthreads();

        float fac[4];
        #pragma unroll
        for (int i = 0; i < 4; i++) fac[i] = srow[ty * 4 + i];
        #pragma unroll
        for (int i = 0; i < 4; i++)
            #pragma unroll
            for (int j = 0; j < 4; j++) o4[i][j] *= fac[i];

        #pragma unroll 8
        for (int k = 0; k < 64; k++) {
            float a[4], b[4];
            #pragma unroll
            for (int i = 0; i < 4; i++) a[i] = Ps[(ty * 4 + i) * 65 + k];
            #pragma unroll
            for (int j = 0; j < 4; j++) b[j] = KVs[k * 65 + tx * 4 + j];
            #pragma unroll
            for (int i = 0; i < 4; i++)
                #pragma unroll
                for (int j = 0; j < 4; j++) o4[i][j] += a[i] * b[j];
        }
        __syncthreads();
    }

    int b = bh >> 4, h = bh & 15;
    #pragma unroll
    for (int i = 0; i < 4; i++) {
        int tg = t0 + ty * 4 + i;
        float inv = 1.0f / lrow[ty * 4 + i];
        #pragma unroll
        for (int j = 0; j < 4; j++) {
            g_attn[((size_t)tg * B_ + b) * D_ + h * HD + tx * 4 + j] = o4[i][j] * inv;
        }
    }
    if (tid < 64)
        g_lse[(size_t)bh * T_ + t0 + tid] = mrow[tid] + logf(lrow[tid]);
}

// ---------------------------------------------------------------------------
// Kernel 3: head-averaged attention weights -> d_out[ROWS*D_ + (b*T+t)*T + s].
// Recomputes score tiles for all heads using stored lse. Zero-fills masked.
// ---------------------------------------------------------------------------
__global__ void avg_kernel(float* __restrict__ out)
{
    __shared__ float Qt[64][65];
    __shared__ float Ks[64][65];

    int b  = blockIdx.z;
    int t0 = blockIdx.y * 64;
    int s0 = blockIdx.x * 64;
    int tx = threadIdx.x, ty = threadIdx.y;
    int tid = ty * 16 + tx;

    float* dst = out + (size_t)ROWS * D_ + (size_t)b * T_ * T_;

    if (blockIdx.x > blockIdx.y) {   // strictly upper triangle: all zeros
        #pragma unroll
        for (int i = 0; i < 4; i++) {
            int tg = t0 + ty * 4 + i;
            #pragma unroll
            for (int j = 0; j < 4; j++)
                dst[(size_t)tg * T_ + s0 + tx * 4 + j] = 0.0f;
        }
        return;
    }

    float acc[4][4] = {};

    for (int h = 0; h < H_; h++) {
        const float* qb = g_qh + (size_t)(b * H_ + h) * T_ * HD;
        const float* kb = g_kh + (size_t)(b * H_ + h) * T_ * HD;
        for (int i = tid; i < 64 * 64; i += 256) {
            int row = i >> 6, d = i & 63;
            Qt[row][d] = qb[(size_t)(t0 + row) * HD + d];
            Ks[row][d] = kb[(size_t)(s0 + row) * HD + d];
        }
        __syncthreads();

        float lse[4];
        #pragma unroll
        for (int i = 0; i < 4; i++)
            lse[i] = g_lse[(size_t)(b * H_ + h) * T_ + t0 + ty * 4 + i];

        float s4[4][4] = {};
        #pragma unroll 8
        for (int d = 0; d < 64; d++) {
            float a[4], bb[4];
            #pragma unroll
            for (int i = 0; i < 4; i++) a[i] = Qt[ty * 4 + i][d];
            #pragma unroll
            for (int j = 0; j < 4; j++) bb[j] = Ks[tx * 4 + j][d];
            #pragma unroll
            for (int i = 0; i < 4; i++)
                #pragma unroll
                for (int j = 0; j < 4; j++) s4[i][j] += a[i] * bb[j];
        }
        #pragma unroll
        for (int i = 0; i < 4; i++) {
            int tg = t0 + ty * 4 + i;
            #pragma unroll
            for (int j = 0; j < 4; j++) {
                int sg = s0 + tx * 4 + j;
                if (sg <= tg) acc[i][j] += expf(s4[i][j] - lse[i]);
            }
        }
        __syncthreads();
    }

    const float invH = 1.0f / (float)H_;
    #pragma unroll
    for (int i = 0; i < 4; i++) {
        int tg = t0 + ty * 4 + i;
        #pragma unroll
        for (int j = 0; j < 4; j++) {
            int sg = s0 + tx * 4 + j;
            dst[(size_t)tg * T_ + sg] = (sg <= tg) ? acc[i][j] * invH : 0.0f;
        }
    }
}

// ---------------------------------------------------------------------------
// Kernel 4: output projection. out[r,o] = attn[r,:] . out_w[o,:] + out_b[o]
// ---------------------------------------------------------------------------
__global__ void outproj_kernel(const float* __restrict__ ow,
                               const float* __restrict__ ob,
                               float* __restrict__ out)
{
    __shared__ float As[64][17];
    __shared__ float Bs[64][17];

    int r0 = blockIdx.y * 64;
    int c0 = blockIdx.x * 64;
    int tx = threadIdx.x, ty = threadIdx.y;
    int tid = ty * 16 + tx;

    float acc[4][4] = {};

    for (int k0 = 0; k0 < D_; k0 += 16) {
        #pragma unroll
        for (int i = 0; i < 4; i++) {
            int idx = tid + i * 256;
            int row = idx >> 4, kk = idx & 15;
            As[row][kk] = g_attn[(size_t)(r0 + row) * D_ + k0 + kk];
            Bs[row][kk] = ow[(size_t)(c0 + row) * D_ + k0 + kk];
        }
        __syncthreads();
        #pragma unroll
        for (int kk = 0; kk < 16; kk++) {
            float a[4], b[4];
            #pragma unroll
            for (int i = 0; i < 4; i++) a[i] = As[ty * 4 + i][kk];
            #pragma unroll
            for (int j = 0; j < 4; j++) b[j] = Bs[tx * 4 + j][kk];
            #pragma unroll
            for (int i = 0; i < 4; i++)
                #pragma unroll
                for (int j = 0; j < 4; j++) acc[i][j] += a[i] * b[j];
        }
        __syncthreads();
    }

    #pragma unroll
    for (int i = 0; i < 4; i++) {
        int r = r0 + ty * 4 + i;
        #pragma unroll
        for (int j = 0; j < 4; j++) {
            int o = c0 + tx * 4 + j;
            out[(size_t)r * D_ + o] = acc[i][j] + ob[o];
        }
    }
}

// ---------------------------------------------------------------------------
extern "C" void kernel_launch(void* const* d_in, const int* in_sizes, int n_in,
                              void* d_out, int out_size)
{
    const float* query = (const float*)d_in[0];
    const float* qw    = (const float*)d_in[1];
    const float* qb    = (const float*)d_in[2];
    const float* kw    = (const float*)d_in[3];
    const float* kb    = (const float*)d_in[4];
    const float* vw    = (const float*)d_in[5];
    const float* vb    = (const float*)d_in[6];
    const float* ow    = (const float*)d_in[7];
    const float* ob    = (const float*)d_in[8];
    float* out = (float*)d_out;

    dim3 blk(16, 16);

    // 1) Q/K/V projections
    proj_kernel<<<dim3(D_ / 64, ROWS / 64, 3), blk>>>(query, qw, qb, kw, kb, vw, vb);

    // 2) flash attention (needs 49,920 B dynamic smem > 48KB default)
    size_t smem = (size_t)3 * 64 * 65 * sizeof(float);
    cudaFuncSetAttribute(flash_kernel, cudaFuncAttributeMaxDynamicSharedMemorySize, (int)smem);
    flash_kernel<<<dim3(T_ / 64, BH), blk, smem>>>();

    // 3) averaged attention weights
    avg_kernel<<<dim3(T_ / 64, T_ / 64, B_), blk>>>(out);

    // 4) output projection
    outproj_kernel<<<dim3(D_ / 64, ROWS / 64), blk>>>(ow, ob, out);
}

// round 2
// speedup vs baseline: 2.5687x; 2.5687x over previous
#include <cuda_runtime.h>
#include <cuda_fp16.h>
#include <math.h>
#include <stdint.h>

#define T_  2048
#define B_  2
#define D_  1024
#define H_  16
#define HD  64
#define ROWS (T_*B_)   // 4096
#define BH  (B_*H_)    // 32
#define NT  (T_/64)    // 32 tiles
#define SCALING 0.125f // 1/sqrt(64)

// ---------------- scratch (static device globals; allocation-free) ----------
__device__ float  g_qh[BH * T_ * HD];          // [bh][t][d]  16MB
__device__ float  g_kh[BH * T_ * HD];
__device__ float  g_vh[BH * T_ * HD];
__device__ float  g_attn[ROWS * D_];           // [t*B+b][h*64+d] 16MB
__device__ float  g_lse [BH * T_];             // final lse per row
__device__ float  g_mloc[BH * T_ * NT];        // running max at each s-tile, 8MB
__device__ __half g_e[(size_t)BH * T_ * T_];   // unnormalized exp tiles, 268MB

// ---------------- helpers ---------------------------------------------------
__device__ __forceinline__ float to_tf32(float x) {
    uint32_t u;
    asm("cvt.rna.tf32.f32 %0, %1;" : "=r"(u) : "f"(x));
    return __uint_as_float(u);
}

__device__ __forceinline__ void mma8(float c[4], const float a[4], const float b[2]) {
    const unsigned* A = reinterpret_cast<const unsigned*>(a);
    const unsigned* B = reinterpret_cast<const unsigned*>(b);
    asm volatile(
        "mma.sync.aligned.m16n8k8.row.col.f32.tf32.tf32.f32 "
        "{%0,%1,%2,%3},{%4,%5,%6,%7},{%8,%9},{%0,%1,%2,%3};"
        : "+f"(c[0]), "+f"(c[1]), "+f"(c[2]), "+f"(c[3])
        : "r"(A[0]), "r"(A[1]), "r"(A[2]), "r"(A[3]), "r"(B[0]), "r"(B[1]));
}

// exp(x) for x <= ~0, ~1e-6 relative accuracy, FMA-pipe only (no MUFU)
__device__ __forceinline__ float fast_exp(float x) {
    const float L = 1.4426950408889634f;
    x = fmaxf(x, -80.0f);
    float t = fmaf(x, L, 12582912.0f);          // 1.5*2^23 magic
    int   i = __float_as_int(t) - 0x4B400000;   // round(x*L)
    float k = t - 12582912.0f;
    float f = fmaf(x, L, -k);                   // f in [-0.5,0.5]
    float p = 1.3333558146e-3f;
    p = fmaf(p, f, 9.6181291076e-3f);
    p = fmaf(p, f, 5.5504108664e-2f);
    p = fmaf(p, f, 2.4022650696e-1f);
    p = fmaf(p, f, 6.9314718056e-1f);
    p = fmaf(p, f, 1.0f);
    return __int_as_float(__float_as_int(p) + (i << 23));
}

// ---------------------------------------------------------------------------
// GEMM (tf32 mma): C[4096x1024] = A @ W^T + bias.
// mode 0/1/2: q/k/v -> head-split scratch (+scale for q). mode 3: out proj -> C.
// Block: 256 thr (8 warps, 4m x 2n), tile 128x128, BK=32.
// ---------------------------------------------------------------------------
__global__ __launch_bounds__(256) void gemm_tf32(
    const float* __restrict__ A,
    const float* __restrict__ W0, const float* __restrict__ Bi0,
    const float* __restrict__ W1, const float* __restrict__ Bi1,
    const float* __restrict__ W2, const float* __restrict__ Bi2,
    float* __restrict__ C, int modeSel)
{
    __shared__ float As[128 * 36];
    __shared__ float Ws[128 * 36];

    int mode = (modeSel < 0) ? (int)blockIdx.z : modeSel;
    const float* W    = (mode == 1) ? W1 : (mode == 2) ? W2 : W0;
    const float* bias = (mode == 1) ? Bi1 : (mode == 2) ? Bi2 : Bi0;
    const float* Ain  = (mode == 3) ? (const float*)g_attn : A;

    int m0 = blockIdx.y * 128;
    int n0 = blockIdx.x * 128;
    int tid = threadIdx.x, lane = tid & 31, warp = tid >> 5;
    int mw = warp >> 1, nw = warp & 1;
    int gid = lane >> 2, tig = lane & 3;

    float acc[2][8][4] = {};

    for (int k0 = 0; k0 < D_; k0 += 32) {
        #pragma unroll
        for (int p = 0; p < 4; p++) {
            int i = p * 256 + tid;          // float4 index 0..1023
            int row = i >> 3, c = (i & 7) * 4;
            float4 va = *(const float4*)(Ain + (size_t)(m0 + row) * D_ + k0 + c);
            float4 vw = *(const float4*)(W   + (size_t)(n0 + row) * D_ + k0 + c);
            float* pa = As + row * 36 + c;
            pa[0] = to_tf32(va.x); pa[1] = to_tf32(va.y);
            pa[2] = to_tf32(va.z); pa[3] = to_tf32(va.w);
            float* pw = Ws + row * 36 + c;
            pw[0] = to_tf32(vw.x); pw[1] = to_tf32(vw.y);
            pw[2] = to_tf32(vw.z); pw[3] = to_tf32(vw.w);
        }
        __syncthreads();
        #pragma unroll
        for (int kk = 0; kk < 4; kk++) {
            float af[2][4];
            #pragma unroll
            for (int mi = 0; mi < 2; mi++) {
                int r = mw * 32 + mi * 16 + gid;
                af[mi][0] = As[r * 36 + kk * 8 + tig];
                af[mi][1] = As[(r + 8) * 36 + kk * 8 + tig];
                af[mi][2] = As[r * 36 + kk * 8 + 4 + tig];
                af[mi][3] = As[(r + 8) * 36 + kk * 8 + 4 + tig];
            }
            float bf[8][2];
            #pragma unroll
            for (int j = 0; j < 8; j++) {
                int n = nw * 64 + j * 8 + gid;
                bf[j][0] = Ws[n * 36 + kk * 8 + tig];
                bf[j][1] = Ws[n * 36 + kk * 8 + 4 + tig];
            }
            #pragma unroll
            for (int mi = 0; mi < 2; mi++)
                #pragma unroll
                for (int j = 0; j < 8; j++)
                    mma8(acc[mi][j], af[mi], bf[j]);
        }
        __syncthreads();
    }

    // epilogue
    float* outp = (mode == 0) ? g_qh : (mode == 1) ? g_kh : (mode == 2) ? g_vh : C;
    #pragma unroll
    for (int mi = 0; mi < 2; mi++) {
        int r = m0 + mw * 32 + mi * 16 + gid;
        #pragma unroll
        for (int j = 0; j < 8; j++) {
            int c = n0 + nw * 64 + j * 8 + tig * 2;
            float b0v = bias[c], b1v = bias[c + 1];
            float2 v0 = { acc[mi][j][0] + b0v, acc[mi][j][1] + b1v };
            float2 v1 = { acc[mi][j][2] + b0v, acc[mi][j][3] + b1v };
            if (mode == 0) { v0.x *= SCALING; v0.y *= SCALING; v1.x *= SCALING; v1.y *= SCALING; }
            if (mode < 3) {
                int h = c >> 6, d = c & 63;
                int t = r >> 1, b = r & 1;
                *(float2*)&outp[((size_t)(b * H_ + h) * T_ + t) * HD + d] = v0;
                int r8 = r + 8; t = r8 >> 1; b = r8 & 1;
                *(float2*)&outp[((size_t)(b * H_ + h) * T_ + t) * HD + d] = v1;
            } else {
                *(float2*)&outp[(size_t)r * D_ + c] = v0;
                *(float2*)&outp[(size_t)(r + 8) * D_ + c] = v1;
            }
        }
    }
}

// ---------------------------------------------------------------------------
// Flash attention (tf32 mma), 64 q-rows per block, 4 warps (16 rows each).
// Stores unnormalized e tiles (fp16) + m_loc + lse for the avg pass.
// Dyn smem: Ks[64][72] | Vs[64][72] | Ps[64][72] (Q lives in Ps initially).
// ---------------------------------------------------------------------------
extern __shared__ float fsm[];
__global__ __launch_bounds__(128) void flash_tf32()
{
    float* Ks = fsm;
    float* Vs = fsm + 64 * 72;
    float* Ps = fsm + 2 * 64 * 72;

    int bh = blockIdx.y, tt = blockIdx.x;
    int t0 = tt * 64;
    int tid = threadIdx.x, lane = tid & 31, w = tid >> 5;
    int gid = lane >> 2, tig = lane & 3;
    int r0 = w * 16 + gid;             // local rows r0, r0+8

    const float* qb = g_qh + (size_t)bh * T_ * HD;
    const float* kb = g_kh + (size_t)bh * T_ * HD;
    const float* vb = g_vh + (size_t)bh * T_ * HD;

    // load Q tile into Ps (tf32)
    {
        int row = tid >> 1, c0 = (tid & 1) * 32;
        #pragma unroll
        for (int i = 0; i < 8; i++) {
            float4 v = *(const float4*)(qb + (size_t)(t0 + row) * HD + c0 + i * 4);
            float* p = Ps + row * 72 + c0 + i * 4;
            p[0] = to_tf32(v.x); p[1] = to_tf32(v.y);
            p[2] = to_tf32(v.z); p[3] = to_tf32(v.w);
        }
    }
    __syncthreads();

    float qf[8][4];
    #pragma unroll
    for (int kk = 0; kk < 8; kk++) {
        qf[kk][0] = Ps[r0 * 72 + kk * 8 + tig];
        qf[kk][1] = Ps[(r0 + 8) * 72 + kk * 8 + tig];
        qf[kk][2] = Ps[r0 * 72 + kk * 8 + 4 + tig];
        qf[kk][3] = Ps[(r0 + 8) * 72 + kk * 8 + 4 + tig];
    }

    float acc_o[8][4] = {};
    float m0v = -1e30f, m1v = -1e30f, l0 = 0.0f, l1 = 0.0f;

    for (int st = 0; st <= tt; st++) {
        int s0 = st * 64;
        __syncthreads();   // protect Ks/Vs/Ps vs previous iteration readers
        {
            int row = tid >> 1, c0 = (tid & 1) * 32;
            #pragma unroll
            for (int i = 0; i < 8; i++) {
                float4 v = *(const float4*)(kb + (size_t)(s0 + row) * HD + c0 + i * 4);
                float* p = Ks + row * 72 + c0 + i * 4;
                p[0] = to_tf32(v.x); p[1] = to_tf32(v.y);
                p[2] = to_tf32(v.z); p[3] = to_tf32(v.w);
                float4 u = *(const float4*)(vb + (size_t)(s0 + row) * HD + c0 + i * 4);
                float* q = Vs + row * 72 + c0 + i * 4;
                q[0] = to_tf32(u.x); q[1] = to_tf32(u.y);
                q[2] = to_tf32(u.z); q[3] = to_tf32(u.w);
            }
        }
        __syncthreads();

        // scores = Q @ K^T
        float sc[8][4] = {};
        #pragma unroll
        for (int j = 0; j < 8; j++) {
            #pragma unroll
            for (int kk = 0; kk < 8; kk++) {
                float bf[2];
                bf[0] = Ks[(j * 8 + gid) * 72 + kk * 8 + tig];
                bf[1] = Ks[(j * 8 + gid) * 72 + kk * 8 + 4 + tig];
                mma8(sc[j], qf[kk], bf);
            }
        }

        if (st == tt) {   // causal mask on diagonal tile
            #pragma unroll
            for (int j = 0; j < 8; j++) {
                int c = j * 8 + tig * 2;
                if (c     > r0)     sc[j][0] = -1e30f;
                if (c + 1 > r0)     sc[j][1] = -1e30f;
                if (c     > r0 + 8) sc[j][2] = -1e30f;
                if (c + 1 > r0 + 8) sc[j][3] = -1e30f;
            }
        }

        // row max (4 lanes per row)
        float mx0 = -1e30f, mx1 = -1e30f;
        #pragma unroll
        for (int j = 0; j < 8; j++) {
            mx0 = fmaxf(mx0, fmaxf(sc[j][0], sc[j][1]));
            mx1 = fmaxf(mx1, fmaxf(sc[j][2], sc[j][3]));
        }
        mx0 = fmaxf(mx0, __shfl_xor_sync(0xffffffffu, mx0, 1));
        mx0 = fmaxf(mx0, __shfl_xor_sync(0xffffffffu, mx0, 2));
        mx1 = fmaxf(mx1, __shfl_xor_sync(0xffffffffu, mx1, 1));
        mx1 = fmaxf(mx1, __shfl_xor_sync(0xffffffffu, mx1, 2));

        float mn0 = fmaxf(m0v, mx0), mn1 = fmaxf(m1v, mx1);
        float fac0 = fast_exp(m0v - mn0), fac1 = fast_exp(m1v - mn1);

        float s0v = 0.0f, s1v = 0.0f;
        #pragma unroll
        for (int j = 0; j < 8; j++) {
            sc[j][0] = fast_exp(sc[j][0] - mn0);
            sc[j][1] = fast_exp(sc[j][1] - mn0);
            sc[j][2] = fast_exp(sc[j][2] - mn1);
            sc[j][3] = fast_exp(sc[j][3] - mn1);
            s0v += sc[j][0] + sc[j][1];
            s1v += sc[j][2] + sc[j][3];
        }
        s0v += __shfl_xor_sync(0xffffffffu, s0v, 1);
        s0v += __shfl_xor_sync(0xffffffffu, s0v, 2);
        s1v += __shfl_xor_sync(0xffffffffu, s1v, 1);
        s1v += __shfl_xor_sync(0xffffffffu, s1v, 2);

        l0 = l0 * fac0 + s0v;
        l1 = l1 * fac1 + s1v;
        m0v = mn0; m1v = mn1;

        #pragma unroll
        for (int j = 0; j < 8; j++) {
            acc_o[j][0] *= fac0; acc_o[j][1] *= fac0;
            acc_o[j][2] *= fac1; acc_o[j][3] *= fac1;
        }

        // write e tile to Ps (tf32-rounded for PV mma)
        #pragma unroll
        for (int j = 0; j < 8; j++) {
            int c = j * 8 + tig * 2;
            Ps[r0 * 72 + c]           = to_tf32(sc[j][0]);
            Ps[r0 * 72 + c + 1]       = to_tf32(sc[j][1]);
            Ps[(r0 + 8) * 72 + c]     = to_tf32(sc[j][2]);
            Ps[(r0 + 8) * 72 + c + 1] = to_tf32(sc[j][3]);
        }
        if (tig == 0) {
            g_mloc[((size_t)bh * T_ + t0 + r0) * NT + st]     = mn0;
            g_mloc[((size_t)bh * T_ + t0 + r0 + 8) * NT + st] = mn1;
        }
        __syncthreads();

        // copy e tile -> g_e (fp16)
        {
            __half2* dst2 = (__half2*)(g_e + ((size_t)(bh * NT + tt) * NT + st) * 4096);
            int row = tid >> 1, c0 = (tid & 1) * 32;
            #pragma unroll
            for (int i = 0; i < 16; i++) {
                float x = Ps[row * 72 + c0 + i * 2];
                float y = Ps[row * 72 + c0 + i * 2 + 1];
                dst2[row * 32 + (c0 >> 1) + i] = __floats2half2_rn(x, y);
            }
        }

        // O += P @ V
        #pragma unroll
        for (int kk = 0; kk < 8; kk++) {
            float pf[4];
            pf[0] = Ps[r0 * 72 + kk * 8 + tig];
            pf[1] = Ps[(r0 + 8) * 72 + kk * 8 + tig];
            pf[2] = Ps[r0 * 72 + kk * 8 + 4 + tig];
            pf[3] = Ps[(r0 + 8) * 72 + kk * 8 + 4 + tig];
            #pragma unroll
            for (int j = 0; j < 8; j++) {
                float bf[2];
                bf[0] = Vs[(kk * 8 + tig) * 72 + j * 8 + gid];
                bf[1] = Vs[(kk * 8 + 4 + tig) * 72 + j * 8 + gid];
                mma8(acc_o[j], pf, bf);
            }
        }
    }

    // epilogue
    int b = bh >> 4, h = bh & 15;
    float inv0 = 1.0f / l0, inv1 = 1.0f / l1;
    #pragma unroll
    for (int j = 0; j < 8; j++) {
        int d = h * 64 + j * 8 + tig * 2;
        float2 v0 = { acc_o[j][0] * inv0, acc_o[j][1] * inv0 };
        float2 v1 = { acc_o[j][2] * inv1, acc_o[j][3] * inv1 };
        *(float2*)&g_attn[((size_t)(t0 + r0) * B_ + b) * D_ + d] = v0;
        *(float2*)&g_attn[((size_t)(t0 + r0 + 8) * B_ + b) * D_ + d] = v1;
    }
    if (tig == 0) {
        g_lse[(size_t)bh * T_ + t0 + r0]     = m0v + logf(l0);
        g_lse[(size_t)bh * T_ + t0 + r0 + 8] = m1v + logf(l1);
    }
}

// ---------------------------------------------------------------------------
// Avg weights: out[b,t,s] = (1/H) * sum_h e[bh,t,s] * exp(m_loc - lse).
// Memory-bound fp16 accumulation; zero-fill strictly-upper tiles.
// ---------------------------------------------------------------------------
__global__ __launch_bounds__(256) void avg_kernel(float* __restrict__ out)
{
    __shared__ float sfac[64];
    int st = blockIdx.x, tt = blockIdx.y, b = blockIdx.z;
    int t0 = tt * 64, s0 = st * 64;
    int tid = threadIdx.x;
    int row = tid >> 2, cseg = (tid & 3) * 16;

    float* dst = out + (size_t)ROWS * D_ + (size_t)b * T_ * T_;
    float4* pout = (float4*)(dst + (size_t)(t0 + row) * T_ + s0 + cseg);

    if (st > tt) {
        float4 z = {0.f, 0.f, 0.f, 0.f};
        pout[0] = z; pout[1] = z; pout[2] = z; pout[3] = z;
        return;
    }

    float acc[16] = {};
    for (int h = 0; h < H_; h++) {
        int bh = b * H_ + h;
        __syncthreads();
        if (tid < 64) {
            float ml = g_mloc[((size_t)bh * T_ + t0 + tid) * NT + st];
            float ls = g_lse[(size_t)bh * T_ + t0 + tid];
            sfac[tid] = fast_exp(ml - ls);
        }
        __syncthreads();
        float fac = sfac[row];
        const uint4* ep = (const uint4*)(g_e + ((size_t)(bh * NT + tt) * NT + st) * 4096
                                         + row * 64 + cseg);
        #pragma unroll
        for (int q2 = 0; q2 < 2; q2++) {
            uint4 u = ep[q2];
            const __half2* hp = (const __half2*)&u;
            #pragma unroll
            for (int i = 0; i < 4; i++) {
                float2 f = __half22float2(hp[i]);
                acc[q2 * 8 + i * 2]     += fac * f.x;
                acc[q2 * 8 + i * 2 + 1] += fac * f.y;
            }
        }
    }
    const float invH = 1.0f / (float)H_;
    #pragma unroll
    for (int q2 = 0; q2 < 4; q2++) {
        float4 v = { acc[q2 * 4] * invH, acc[q2 * 4 + 1] * invH,
                     acc[q2 * 4 + 2] * invH, acc[q2 * 4 + 3] * invH };
        pout[q2] = v;
    }
}

// ---------------------------------------------------------------------------
extern "C" void kernel_launch(void* const* d_in, const int* in_sizes, int n_in,
                              void* d_out, int out_size)
{
    const float* query = (const float*)d_in[0];
    const float* qw = (const float*)d_in[1];
    const float* qb = (const float*)d_in[2];
    const float* kw = (const float*)d_in[3];
    const float* kb = (const float*)d_in[4];
    const float* vw = (const float*)d_in[5];
    const float* vb = (const float*)d_in[6];
    const float* ow = (const float*)d_in[7];
    const float* ob = (const float*)d_in[8];
    float* out = (float*)d_out;

    // 1) fused Q/K/V projections (tf32 mma)
    gemm_tf32<<<dim3(8, 32, 3), 256>>>(query, qw, qb, kw, kb, vw, vb, nullptr, -1);

    // 2) flash attention (tf32 mma) + e/mloc/lse side outputs
    size_t smem = (size_t)3 * 64 * 72 * sizeof(float);   // 55,296 B
    cudaFuncSetAttribute(flash_tf32, cudaFuncAttributeMaxDynamicSharedMemorySize, (int)smem);
    flash_tf32<<<dim3(NT, BH), 128, smem>>>();

    // 3) averaged attention weights (memory-bound fp16 accumulation)
    avg_kernel<<<dim3(NT, NT, B_), 256>>>(out);

    // 4) output projection (tf32 mma)
    gemm_tf32<<<dim3(8, 32, 1), 256>>>(nullptr, ow, ob, ow, ob, ow, ob, out, 3);
}

// round 3
// speedup vs baseline: 3.4884x; 1.3580x over previous
#include <cuda_runtime.h>
#include <cuda_fp16.h>
#include <math.h>
#include <stdint.h>

#define T_  2048
#define B_  2
#define D_  1024
#define H_  16
#define HD  64
#define ROWS (T_*B_)   // 4096
#define BH  (B_*H_)    // 32
#define NT  (T_/64)    // 32 (64-col score tiles)
#define NQT (T_/128)   // 16 (128-row q blocks)
#define SCALING 0.125f // 1/sqrt(64)

// ---------------- scratch (static device globals; allocation-free) ----------
__device__ float  g_qh[BH * T_ * HD];          // [bh][t][d]  16MB
__device__ float  g_kh[BH * T_ * HD];
__device__ float  g_vh[BH * T_ * HD];
__device__ float  g_attn[ROWS * D_];           // [t*B+b][h*64+d] 16MB
__device__ float  g_lse [BH * T_];             // final lse per row
__device__ float  g_mloc[BH * T_ * NT];        // running max at each s-tile
__device__ __half g_e[(size_t)BH * T_ * T_];   // unnormalized exp tiles

// ---------------- helpers ---------------------------------------------------
__device__ __forceinline__ float to_tf32(float x) {
    uint32_t u;
    asm("cvt.rna.tf32.f32 %0, %1;" : "=r"(u) : "f"(x));
    return __uint_as_float(u);
}

__device__ __forceinline__ void mma8(float c[4], const float a[4], const float b[2]) {
    const unsigned* A = reinterpret_cast<const unsigned*>(a);
    const unsigned* B = reinterpret_cast<const unsigned*>(b);
    asm volatile(
        "mma.sync.aligned.m16n8k8.row.col.f32.tf32.tf32.f32 "
        "{%0,%1,%2,%3},{%4,%5,%6,%7},{%8,%9},{%0,%1,%2,%3};"
        : "+f"(c[0]), "+f"(c[1]), "+f"(c[2]), "+f"(c[3])
        : "r"(A[0]), "r"(A[1]), "r"(A[2]), "r"(A[3]), "r"(B[0]), "r"(B[1]));
}

// exp(x) for x <= ~0, FMA-pipe only (no MUFU)
__device__ __forceinline__ float fast_exp(float x) {
    const float L = 1.4426950408889634f;
    x = fmaxf(x, -80.0f);
    float t = fmaf(x, L, 12582912.0f);          // 1.5*2^23 magic
    int   i = __float_as_int(t) - 0x4B400000;
    float k = t - 12582912.0f;
    float f = fmaf(x, L, -k);
    float p = 1.3333558146e-3f;
    p = fmaf(p, f, 9.6181291076e-3f);
    p = fmaf(p, f, 5.5504108664e-2f);
    p = fmaf(p, f, 2.4022650696e-1f);
    p = fmaf(p, f, 6.9314718056e-1f);
    p = fmaf(p, f, 1.0f);
    return __int_as_float(__float_as_int(p) + (i << 23));
}

// ---------------------------------------------------------------------------
// GEMM (tf32 mma): C[4096x1024] = A @ W^T + bias.
// mode 0/1/2: q/k/v -> head-split scratch (+scale for q). mode 3: out proj -> C.
// ---------------------------------------------------------------------------
__global__ __launch_bounds__(256) void gemm_tf32(
    const float* __restrict__ A,
    const float* __restrict__ W0, const float* __restrict__ Bi0,
    const float* __restrict__ W1, const float* __restrict__ Bi1,
    const float* __restrict__ W2, const float* __restrict__ Bi2,
    float* __restrict__ C, int modeSel)
{
    __shared__ float As[128 * 36];
    __shared__ float Ws[128 * 36];

    int mode = (modeSel < 0) ? (int)blockIdx.z : modeSel;
    const float* W    = (mode == 1) ? W1 : (mode == 2) ? W2 : W0;
    const float* bias = (mode == 1) ? Bi1 : (mode == 2) ? Bi2 : Bi0;
    const float* Ain  = (mode == 3) ? (const float*)g_attn : A;

    int m0 = blockIdx.y * 128;
    int n0 = blockIdx.x * 128;
    int tid = threadIdx.x, lane = tid & 31, warp = tid >> 5;
    int mw = warp >> 1, nw = warp & 1;
    int gid = lane >> 2, tig = lane & 3;

    float acc[2][8][4] = {};

    for (int k0 = 0; k0 < D_; k0 += 32) {
        #pragma unroll
        for (int p = 0; p < 4; p++) {
            int i = p * 256 + tid;
            int row = i >> 3, c = (i & 7) * 4;
            float4 va = *(const float4*)(Ain + (size_t)(m0 + row) * D_ + k0 + c);
            float4 vw = *(const float4*)(W   + (size_t)(n0 + row) * D_ + k0 + c);
            float* pa = As + row * 36 + c;
            pa[0] = to_tf32(va.x); pa[1] = to_tf32(va.y);
            pa[2] = to_tf32(va.z); pa[3] = to_tf32(va.w);
            float* pw = Ws + row * 36 + c;
            pw[0] = to_tf32(vw.x); pw[1] = to_tf32(vw.y);
            pw[2] = to_tf32(vw.z); pw[3] = to_tf32(vw.w);
        }
        __syncthreads();
        #pragma unroll
        for (int kk = 0; kk < 4; kk++) {
            float af[2][4];
            #pragma unroll
            for (int mi = 0; mi < 2; mi++) {
                int r = mw * 32 + mi * 16 + gid;
                af[mi][0] = As[r * 36 + kk * 8 + tig];
                af[mi][1] = As[(r + 8) * 36 + kk * 8 + tig];
                af[mi][2] = As[r * 36 + kk * 8 + 4 + tig];
                af[mi][3] = As[(r + 8) * 36 + kk * 8 + 4 + tig];
            }
            float bf[8][2];
            #pragma unroll
            for (int j = 0; j < 8; j++) {
                int n = nw * 64 + j * 8 + gid;
                bf[j][0] = Ws[n * 36 + kk * 8 + tig];
                bf[j][1] = Ws[n * 36 + kk * 8 + 4 + tig];
            }
            #pragma unroll
            for (int mi = 0; mi < 2; mi++)
                #pragma unroll
                for (int j = 0; j < 8; j++)
                    mma8(acc[mi][j], af[mi], bf[j]);
        }
        __syncthreads();
    }

    float* outp = (mode == 0) ? g_qh : (mode == 1) ? g_kh : (mode == 2) ? g_vh : C;
    #pragma unroll
    for (int mi = 0; mi < 2; mi++) {
        int r = m0 + mw * 32 + mi * 16 + gid;
        #pragma unroll
        for (int j = 0; j < 8; j++) {
            int c = n0 + nw * 64 + j * 8 + tig * 2;
            float b0v = bias[c], b1v = bias[c + 1];
            float2 v0 = { acc[mi][j][0] + b0v, acc[mi][j][1] + b1v };
            float2 v1 = { acc[mi][j][2] + b0v, acc[mi][j][3] + b1v };
            if (mode == 0) { v0.x *= SCALING; v0.y *= SCALING; v1.x *= SCALING; v1.y *= SCALING; }
            if (mode < 3) {
                int h = c >> 6, d = c & 63;
                int t = r >> 1, b = r & 1;
                *(float2*)&outp[((size_t)(b * H_ + h) * T_ + t) * HD + d] = v0;
                int r8 = r + 8; t = r8 >> 1; b = r8 & 1;
                *(float2*)&outp[((size_t)(b * H_ + h) * T_ + t) * HD + d] = v1;
            } else {
                *(float2*)&outp[(size_t)r * D_ + c] = v0;
                *(float2*)&outp[(size_t)(r + 8) * D_ + c] = v1;
            }
        }
    }
}

// ---------------------------------------------------------------------------
// Flash attention (tf32 mma): 128 q-rows per block, 8 warps (16 rows each).
// P stays in registers (shuffle-based fragment relayout); e tiles written
// straight from fragments. 2 syncthreads per s-tile.
// ---------------------------------------------------------------------------
__global__ __launch_bounds__(256) void flash_tf32()
{
    __shared__ float sm[2 * 64 * 72];     // Ks | Vs (also Q staging pre-loop)
    float* Ks = sm;
    float* Vs = sm + 64 * 72;

    int bh = blockIdx.y;
    int tt = (int)(gridDim.x - 1 - blockIdx.x);   // heavy blocks first
    int t0 = tt * 128;
    int tid = threadIdx.x, lane = tid & 31, w = tid >> 5;
    int gid = lane >> 2, tig = lane & 3;
    int lrow = w * 16 + gid;              // local rows lrow, lrow+8 (0..127)

    const float* qb = g_qh + (size_t)bh * T_ * HD;
    const float* kb = g_kh + (size_t)bh * T_ * HD;
    const float* vb = g_vh + (size_t)bh * T_ * HD;

    // ---- stage Q (128x64, tf32) through smem, pull fragments to registers
    {
        int row = tid >> 1, c0 = (tid & 1) * 32;
        #pragma unroll
        for (int i = 0; i < 8; i++) {
            float4 v = *(const float4*)(qb + (size_t)(t0 + row) * HD + c0 + i * 4);
            float* p = sm + row * 72 + c0 + i * 4;
            p[0] = to_tf32(v.x); p[1] = to_tf32(v.y);
            p[2] = to_tf32(v.z); p[3] = to_tf32(v.w);
        }
    }
    __syncthreads();
    float qf[8][4];
    #pragma unroll
    for (int kk = 0; kk < 8; kk++) {
        qf[kk][0] = sm[lrow * 72 + kk * 8 + tig];
        qf[kk][1] = sm[(lrow + 8) * 72 + kk * 8 + tig];
        qf[kk][2] = sm[lrow * 72 + kk * 8 + 4 + tig];
        qf[kk][3] = sm[(lrow + 8) * 72 + kk * 8 + 4 + tig];
    }

    float acc_o[8][4] = {};
    float m0v = -1e30f, m1v = -1e30f, l0 = 0.0f, l1 = 0.0f;

    int tt64 = tt * 2 + (lrow >= 64 ? 1 : 0);
    int rloc = lrow & 63;
    int nst = 2 * tt + 2;

    for (int st = 0; st < nst; st++) {
        int s0 = st * 64;
        __syncthreads();   // previous iter done with Ks/Vs
        {
            int row = tid >> 2, c0 = (tid & 3) * 16;
            #pragma unroll
            for (int i = 0; i < 4; i++) {
                float4 v = *(const float4*)(kb + (size_t)(s0 + row) * HD + c0 + i * 4);
                float* p = Ks + row * 72 + c0 + i * 4;
                p[0] = to_tf32(v.x); p[1] = to_tf32(v.y);
                p[2] = to_tf32(v.z); p[3] = to_tf32(v.w);
                float4 u = *(const float4*)(vb + (size_t)(s0 + row) * HD + c0 + i * 4);
                float* q = Vs + row * 72 + c0 + i * 4;
                q[0] = to_tf32(u.x); q[1] = to_tf32(u.y);
                q[2] = to_tf32(u.z); q[3] = to_tf32(u.w);
            }
        }
        __syncthreads();

        // ---- scores = Q @ K^T (16x64 per warp)
        float sc[8][4] = {};
        #pragma unroll
        for (int kk = 0; kk < 8; kk++) {
            #pragma unroll
            for (int j = 0; j < 8; j++) {
                float bf[2];
                bf[0] = Ks[(j * 8 + gid) * 72 + kk * 8 + tig];
                bf[1] = Ks[(j * 8 + gid) * 72 + kk * 8 + 4 + tig];
                mma8(sc[j], qf[kk], bf);
            }
        }

        // ---- causal mask (only the last two s-tiles can touch the diagonal)
        if (st >= 2 * tt) {
            int rg0 = t0 + lrow, rg1 = rg0 + 8;
            #pragma unroll
            for (int j = 0; j < 8; j++) {
                int cg = s0 + j * 8 + 2 * tig;
                if (cg     > rg0) sc[j][0] = -1e30f;
                if (cg + 1 > rg0) sc[j][1] = -1e30f;
                if (cg     > rg1) sc[j][2] = -1e30f;
                if (cg + 1 > rg1) sc[j][3] = -1e30f;
            }
        }

        // ---- online softmax (rows r: lanes with same gid; reduce over 4 lanes)
        float mx0 = -1e30f, mx1 = -1e30f;
        #pragma unroll
        for (int j = 0; j < 8; j++) {
            mx0 = fmaxf(mx0, fmaxf(sc[j][0], sc[j][1]));
            mx1 = fmaxf(mx1, fmaxf(sc[j][2], sc[j][3]));
        }
        mx0 = fmaxf(mx0, __shfl_xor_sync(0xffffffffu, mx0, 1));
        mx0 = fmaxf(mx0, __shfl_xor_sync(0xffffffffu, mx0, 2));
        mx1 = fmaxf(mx1, __shfl_xor_sync(0xffffffffu, mx1, 1));
        mx1 = fmaxf(mx1, __shfl_xor_sync(0xffffffffu, mx1, 2));

        float mn0 = fmaxf(m0v, mx0), mn1 = fmaxf(m1v, mx1);
        float fac0 = fast_exp(m0v - mn0), fac1 = fast_exp(m1v - mn1);

        float s0v = 0.0f, s1v = 0.0f;
        #pragma unroll
        for (int j = 0; j < 8; j++) {
            sc[j][0] = fast_exp(sc[j][0] - mn0);
            sc[j][1] = fast_exp(sc[j][1] - mn0);
            sc[j][2] = fast_exp(sc[j][2] - mn1);
            sc[j][3] = fast_exp(sc[j][3] - mn1);
            s0v += sc[j][0] + sc[j][1];
            s1v += sc[j][2] + sc[j][3];
        }
        s0v += __shfl_xor_sync(0xffffffffu, s0v, 1);
        s0v += __shfl_xor_sync(0xffffffffu, s0v, 2);
        s1v += __shfl_xor_sync(0xffffffffu, s1v, 1);
        s1v += __shfl_xor_sync(0xffffffffu, s1v, 2);

        l0 = l0 * fac0 + s0v;
        l1 = l1 * fac1 + s1v;
        m0v = mn0; m1v = mn1;

        #pragma unroll
        for (int j = 0; j < 8; j++) {
            acc_o[j][0] *= fac0; acc_o[j][1] *= fac0;
            acc_o[j][2] *= fac1; acc_o[j][3] *= fac1;
        }

        // ---- side outputs straight from fragments
        __half* tb = g_e + ((size_t)(bh * NT + tt64) * NT + st) * 4096;
        #pragma unroll
        for (int j = 0; j < 8; j++) {
            int c = j * 8 + 2 * tig;
            *(__half2*)(tb + rloc * 64 + c)       = __floats2half2_rn(sc[j][0], sc[j][1]);
            *(__half2*)(tb + (rloc + 8) * 64 + c) = __floats2half2_rn(sc[j][2], sc[j][3]);
        }
        if (tig == 0) {
            g_mloc[((size_t)bh * T_ + t0 + lrow) * NT + st]     = mn0;
            g_mloc[((size_t)bh * T_ + t0 + lrow + 8) * NT + st] = mn1;
        }

        // ---- O += P @ V, P relayout via intra-quad shuffles (no smem)
        int src0 = (lane & ~3) | (tig >> 1);
        int src2 = src0 + 2;
        bool odd = tig & 1;
        #pragma unroll
        for (int kk = 0; kk < 8; kk++) {
            float e00 = __shfl_sync(0xffffffffu, sc[kk][0], src0);
            float e01 = __shfl_sync(0xffffffffu, sc[kk][1], src0);
            float e10 = __shfl_sync(0xffffffffu, sc[kk][2], src0);
            float e11 = __shfl_sync(0xffffffffu, sc[kk][3], src0);
            float f00 = __shfl_sync(0xffffffffu, sc[kk][0], src2);
            float f01 = __shfl_sync(0xffffffffu, sc[kk][1], src2);
            float f10 = __shfl_sync(0xffffffffu, sc[kk][2], src2);
            float f11 = __shfl_sync(0xffffffffu, sc[kk][3], src2);
            float pf[4];
            pf[0] = to_tf32(odd ? e01 : e00);
            pf[1] = to_tf32(odd ? e11 : e10);
            pf[2] = to_tf32(odd ? f01 : f00);
            pf[3] = to_tf32(odd ? f11 : f10);
            #pragma unroll
            for (int j = 0; j < 8; j++) {
                float bf[2];
                bf[0] = Vs[(kk * 8 + tig) * 72 + j * 8 + gid];
                bf[1] = Vs[(kk * 8 + 4 + tig) * 72 + j * 8 + gid];
                mma8(acc_o[j], pf, bf);
            }
        }
    }

    // ---- epilogue
    int b = bh >> 4, h = bh & 15;
    float inv0 = 1.0f / l0, inv1 = 1.0f / l1;
    #pragma unroll
    for (int j = 0; j < 8; j++) {
        int d = h * 64 + j * 8 + 2 * tig;
        float2 v0 = { acc_o[j][0] * inv0, acc_o[j][1] * inv0 };
        float2 v1 = { acc_o[j][2] * inv1, acc_o[j][3] * inv1 };
        *(float2*)&g_attn[((size_t)(t0 + lrow) * B_ + b) * D_ + d] = v0;
        *(float2*)&g_attn[((size_t)(t0 + lrow + 8) * B_ + b) * D_ + d] = v1;
    }
    if (tig == 0) {
        g_lse[(size_t)bh * T_ + t0 + lrow]     = m0v + logf(l0);
        g_lse[(size_t)bh * T_ + t0 + lrow + 8] = m1v + logf(l1);
    }
}

// ---------------------------------------------------------------------------
// Avg weights: out[b,t,s] = (1/H) * sum_h e[bh,t,s] * exp(m_loc - lse).
// ---------------------------------------------------------------------------
__global__ __launch_bounds__(256) void avg_kernel(float* __restrict__ out)
{
    __shared__ float sfac[64];
    int st = blockIdx.x, tt = blockIdx.y, b = blockIdx.z;
    int t0 = tt * 64, s0 = st * 64;
    int tid = threadIdx.x;
    int row = tid >> 2, cseg = (tid & 3) * 16;

    float* dst = out + (size_t)ROWS * D_ + (size_t)b * T_ * T_;
    float4* pout = (float4*)(dst + (size_t)(t0 + row) * T_ + s0 + cseg);

    if (st > tt) {
        float4 z = {0.f, 0.f, 0.f, 0.f};
        pout[0] = z; pout[1] = z; pout[2] = z; pout[3] = z;
        return;
    }

    float acc[16] = {};
    for (int h = 0; h < H_; h++) {
        int bh = b * H_ + h;
        __syncthreads();
        if (tid < 64) {
            float ml = g_mloc[((size_t)bh * T_ + t0 + tid) * NT + st];
            float ls = g_lse[(size_t)bh * T_ + t0 + tid];
            sfac[tid] = fast_exp(ml - ls);
        }
        __syncthreads();
        float fac = sfac[row];
        const uint4* ep = (const uint4*)(g_e + ((size_t)(bh * NT + tt) * NT + st) * 4096
                                         + row * 64 + cseg);
        #pragma unroll
        for (int q2 = 0; q2 < 2; q2++) {
            uint4 u = ep[q2];
            const __half2* hp = (const __half2*)&u;
            #pragma unroll
            for (int i = 0; i < 4; i++) {
                float2 f = __half22float2(hp[i]);
                acc[q2 * 8 + i * 2]     += fac * f.x;
                acc[q2 * 8 + i * 2 + 1] += fac * f.y;
            }
        }
    }
    const float invH = 1.0f / (float)H_;
    #pragma unroll
    for (int q2 = 0; q2 < 4; q2++) {
        float4 v = { acc[q2 * 4] * invH, acc[q2 * 4 + 1] * invH,
                     acc[q2 * 4 + 2] * invH, acc[q2 * 4 + 3] * invH };
        pout[q2] = v;
    }
}

// ---------------------------------------------------------------------------
extern "C" void kernel_launch(void* const* d_in, const int* in_sizes, int n_in,
                              void* d_out, int out_size)
{
    const float* query = (const float*)d_in[0];
    const float* qw = (const float*)d_in[1];
    const float* qb = (const float*)d_in[2];
    const float* kw = (const float*)d_in[3];
    const float* kb = (const float*)d_in[4];
    const float* vw = (const float*)d_in[5];
    const float* vb = (const float*)d_in[6];
    const float* ow = (const float*)d_in[7];
    const float* ob = (const float*)d_in[8];
    float* out = (float*)d_out;

    // 1) fused Q/K/V projections (tf32 mma)
    gemm_tf32<<<dim3(8, 32, 3), 256>>>(query, qw, qb, kw, kb, vw, vb, nullptr, -1);

    // 2) flash attention (tf32 mma), 128-row q tiles, heavy blocks first
    flash_tf32<<<dim3(NQT, BH), 256>>>();

    // 3) averaged attention weights (memory-bound fp16 accumulation)
    avg_kernel<<<dim3(NT, NT, B_), 256>>>(out);

    // 4) output projection (tf32 mma)
    gemm_tf32<<<dim3(8, 32, 1), 256>>>(nullptr, ow, ob, ow, ob, ow, ob, out, 3);
}

// round 4
// speedup vs baseline: 3.6616x; 1.0496x over previous
#include <cuda_runtime.h>
#include <cuda_fp16.h>
#include <math.h>
#include <stdint.h>

#define T_  2048
#define B_  2
#define D_  1024
#define H_  16
#define HD  64
#define ROWS (T_*B_)   // 4096
#define BH  (B_*H_)    // 32
#define NT  (T_/64)    // 32 (64-col score tiles)
#define NQT (T_/128)   // 16 (128-row q blocks)
#define SCALING 0.125f

// ---------------- scratch (static device globals) ---------------------------
__device__ float  g_x [ROWS * D_];             // tf32-rounded input
__device__ float  g_wq[D_ * D_], g_wk[D_ * D_], g_wv[D_ * D_], g_wo[D_ * D_];
__device__ float  g_qh[BH * T_ * HD];          // rounded q/k/v, head-split
__device__ float  g_kh[BH * T_ * HD];
__device__ float  g_vh[BH * T_ * HD];
__device__ float  g_attn[ROWS * D_];           // rounded attn output
__device__ float  g_lse [BH * T_];
__device__ float  g_mloc[BH * T_ * NT];
__device__ __half g_e[(size_t)BH * T_ * T_];

// ---------------- helpers ---------------------------------------------------
__device__ __forceinline__ float to_tf32(float x) {
    uint32_t u;
    asm("cvt.rna.tf32.f32 %0, %1;" : "=r"(u) : "f"(x));
    return __uint_as_float(u);
}

__device__ __forceinline__ void mma8(float c[4], const float a[4], const float b[2]) {
    const unsigned* A = reinterpret_cast<const unsigned*>(a);
    const unsigned* B = reinterpret_cast<const unsigned*>(b);
    asm volatile(
        "mma.sync.aligned.m16n8k8.row.col.f32.tf32.tf32.f32 "
        "{%0,%1,%2,%3},{%4,%5,%6,%7},{%8,%9},{%0,%1,%2,%3};"
        : "+f"(c[0]), "+f"(c[1]), "+f"(c[2]), "+f"(c[3])
        : "r"(A[0]), "r"(A[1]), "r"(A[2]), "r"(A[3]), "r"(B[0]), "r"(B[1]));
}

__device__ __forceinline__ void cp16(void* dst_smem, const float* src) {
    uint32_t d = (uint32_t)__cvta_generic_to_shared(dst_smem);
    asm volatile("cp.async.cg.shared.global [%0], [%1], 16;" :: "r"(d), "l"(src));
}
#define CP_COMMIT() asm volatile("cp.async.commit_group;")
template<int N> __device__ __forceinline__ void cp_wait() {
    asm volatile("cp.async.wait_group %0;" :: "n"(N));
}

// exp(x) for x <= ~0, FMA-pipe only
__device__ __forceinline__ float fast_exp(float x) {
    const float L = 1.4426950408889634f;
    x = fmaxf(x, -80.0f);
    float t = fmaf(x, L, 12582912.0f);
    int   i = __float_as_int(t) - 0x4B400000;
    float k = t - 12582912.0f;
    float f = fmaf(x, L, -k);
    float p = 1.3333558146e-3f;
    p = fmaf(p, f, 9.6181291076e-3f);
    p = fmaf(p, f, 5.5504108664e-2f);
    p = fmaf(p, f, 2.4022650696e-1f);
    p = fmaf(p, f, 6.9314718056e-1f);
    p = fmaf(p, f, 1.0f);
    return __int_as_float(__float_as_int(p) + (i << 23));
}

// ---------------------------------------------------------------------------
// Prep: tf32-round query + weights into scratch (float4 grid-stride).
// ---------------------------------------------------------------------------
__global__ __launch_bounds__(256) void prep_round(
    const float* __restrict__ q,  const float* __restrict__ wq,
    const float* __restrict__ wk, const float* __restrict__ wv,
    const float* __restrict__ wo)
{
    const size_t NX = (size_t)ROWS * D_ / 4;   // 1,048,576
    const size_t NW = (size_t)D_ * D_ / 4;     // 262,144
    size_t i = (size_t)blockIdx.x * 256 + threadIdx.x;
    const float* src; float* dst; size_t off;
    if      (i < NX)          { src = q;  dst = g_x;  off = i; }
    else if (i < NX + NW)     { src = wq; dst = g_wq; off = i - NX; }
    else if (i < NX + 2*NW)   { src = wk; dst = g_wk; off = i - NX - NW; }
    else if (i < NX + 3*NW)   { src = wv; dst = g_wv; off = i - NX - 2*NW; }
    else                      { src = wo; dst = g_wo; off = i - NX - 3*NW; }
    float4 v = ((const float4*)src)[off];
    v.x = to_tf32(v.x); v.y = to_tf32(v.y);
    v.z = to_tf32(v.z); v.w = to_tf32(v.w);
    ((float4*)dst)[off] = v;
}

// ---------------------------------------------------------------------------
// GEMM (tf32 mma, cp.async 2-stage): C[4096x1024] = A @ W^T + bias.
// modes 0/1/2: A=g_x, W=g_wq/wk/wv -> rounded head-split q/k/v (+scale for q).
// mode 3: A=g_attn, W=g_wo -> final out (unrounded).
// Dyn smem: 2 stages x (A 128x36 + W 128x36) = 73,728 B.
// ---------------------------------------------------------------------------
extern __shared__ float dynsm[];

__device__ __forceinline__ void gemm_load_tile(
    float* AsS, float* WsS, const float* Ain, const float* W,
    int m0, int n0, int k0, int tid)
{
    #pragma unroll
    for (int p = 0; p < 4; p++) {
        int i = p * 256 + tid;
        int row = i >> 3, c = (i & 7) * 4;
        cp16(AsS + row * 36 + c, Ain + (size_t)(m0 + row) * D_ + k0 + c);
        cp16(WsS + row * 36 + c, W   + (size_t)(n0 + row) * D_ + k0 + c);
    }
    CP_COMMIT();
}

__global__ __launch_bounds__(256) void gemm_tf32(
    const float* __restrict__ Bi0, const float* __restrict__ Bi1,
    const float* __restrict__ Bi2, float* __restrict__ C, int modeSel)
{
    int mode = (modeSel < 0) ? (int)blockIdx.z : modeSel;
    const float* W    = (mode == 1) ? g_wk : (mode == 2) ? g_wv : (mode == 3) ? g_wo : g_wq;
    const float* bias = (mode == 1) ? Bi1 : (mode == 2) ? Bi2 : Bi0;
    const float* Ain  = (mode == 3) ? (const float*)g_attn : (const float*)g_x;

    int m0 = blockIdx.y * 128;
    int n0 = blockIdx.x * 128;
    int tid = threadIdx.x, lane = tid & 31, warp = tid >> 5;
    int mw = warp >> 1, nw = warp & 1;
    int gid = lane >> 2, tig = lane & 3;

    float acc[2][8][4] = {};

    gemm_load_tile(dynsm, dynsm + 4608, Ain, W, m0, n0, 0, tid);

    for (int kt = 0; kt < 32; kt++) {
        int s = kt & 1;
        float* AsS = dynsm + s * 9216;
        float* WsS = AsS + 4608;
        if (kt + 1 < 32) {
            float* An = dynsm + (s ^ 1) * 9216;
            gemm_load_tile(An, An + 4608, Ain, W, m0, n0, (kt + 1) * 32, tid);
            cp_wait<1>();
        } else {
            cp_wait<0>();
        }
        __syncthreads();

        #pragma unroll
        for (int kk = 0; kk < 4; kk++) {
            float af[2][4];
            #pragma unroll
            for (int mi = 0; mi < 2; mi++) {
                int r = mw * 32 + mi * 16 + gid;
                af[mi][0] = AsS[r * 36 + kk * 8 + tig];
                af[mi][1] = AsS[(r + 8) * 36 + kk * 8 + tig];
                af[mi][2] = AsS[r * 36 + kk * 8 + 4 + tig];
                af[mi][3] = AsS[(r + 8) * 36 + kk * 8 + 4 + tig];
            }
            float bf[8][2];
            #pragma unroll
            for (int j = 0; j < 8; j++) {
                int n = nw * 64 + j * 8 + gid;
                bf[j][0] = WsS[n * 36 + kk * 8 + tig];
                bf[j][1] = WsS[n * 36 + kk * 8 + 4 + tig];
            }
            #pragma unroll
            for (int mi = 0; mi < 2; mi++)
                #pragma unroll
                for (int j = 0; j < 8; j++)
                    mma8(acc[mi][j], af[mi], bf[j]);
        }
        __syncthreads();
    }

    float* outp = (mode == 0) ? g_qh : (mode == 1) ? g_kh : (mode == 2) ? g_vh : C;
    #pragma unroll
    for (int mi = 0; mi < 2; mi++) {
        int r = m0 + mw * 32 + mi * 16 + gid;
        #pragma unroll
        for (int j = 0; j < 8; j++) {
            int c = n0 + nw * 64 + j * 8 + tig * 2;
            float b0v = bias[c], b1v = bias[c + 1];
            float2 v0 = { acc[mi][j][0] + b0v, acc[mi][j][1] + b1v };
            float2 v1 = { acc[mi][j][2] + b0v, acc[mi][j][3] + b1v };
            if (mode == 0) { v0.x *= SCALING; v0.y *= SCALING; v1.x *= SCALING; v1.y *= SCALING; }
            if (mode < 3) {
                v0.x = to_tf32(v0.x); v0.y = to_tf32(v0.y);
                v1.x = to_tf32(v1.x); v1.y = to_tf32(v1.y);
                int h = c >> 6, d = c & 63;
                int t = r >> 1, b = r & 1;
                *(float2*)&outp[((size_t)(b * H_ + h) * T_ + t) * HD + d] = v0;
                int r8 = r + 8; t = r8 >> 1; b = r8 & 1;
                *(float2*)&outp[((size_t)(b * H_ + h) * T_ + t) * HD + d] = v1;
            } else {
                *(float2*)&outp[(size_t)r * D_ + c] = v0;
                *(float2*)&outp[(size_t)(r + 8) * D_ + c] = v1;
            }
        }
    }
}

// ---------------------------------------------------------------------------
// Flash attention (tf32 mma, cp.async 2-stage K/V): 128 q-rows per block.
// Dyn smem: K[2] + V[2] buffers of 64x72 floats = 73,728 B (Q staged there first).
// ---------------------------------------------------------------------------
__device__ __forceinline__ void flash_load_kv(
    float* Kst, float* Vst, const float* kb, const float* vb, int s0, int tid)
{
    int row = tid >> 2, c0 = (tid & 3) * 16;
    const float* kp = kb + (size_t)(s0 + row) * HD + c0;
    const float* vp = vb + (size_t)(s0 + row) * HD + c0;
    float* kd = Kst + row * 72 + c0;
    float* vd = Vst + row * 72 + c0;
    #pragma unroll
    for (int i = 0; i < 4; i++) {
        cp16(kd + i * 4, kp + i * 4);
        cp16(vd + i * 4, vp + i * 4);
    }
    CP_COMMIT();
}

__global__ __launch_bounds__(256) void flash_tf32()
{
    int bh = blockIdx.y;
    int tt = (int)(gridDim.x - 1 - blockIdx.x);   // heavy blocks first
    int t0 = tt * 128;
    int tid = threadIdx.x, lane = tid & 31, w = tid >> 5;
    int gid = lane >> 2, tig = lane & 3;
    int lrow = w * 16 + gid;

    const float* qb = g_qh + (size_t)bh * T_ * HD;
    const float* kb = g_kh + (size_t)bh * T_ * HD;
    const float* vb = g_vh + (size_t)bh * T_ * HD;

    // ---- stage Q (128x64) through smem, pull fragments (values pre-rounded)
    {
        int row = tid >> 1, c0 = (tid & 1) * 32;
        #pragma unroll
        for (int i = 0; i < 8; i++) {
            float4 v = *(const float4*)(qb + (size_t)(t0 + row) * HD + c0 + i * 4);
            *(float4*)(dynsm + row * 72 + c0 + i * 4) = v;
        }
    }
    __syncthreads();
    float qf[8][4];
    #pragma unroll
    for (int kk = 0; kk < 8; kk++) {
        qf[kk][0] = dynsm[lrow * 72 + kk * 8 + tig];
        qf[kk][1] = dynsm[(lrow + 8) * 72 + kk * 8 + tig];
        qf[kk][2] = dynsm[lrow * 72 + kk * 8 + 4 + tig];
        qf[kk][3] = dynsm[(lrow + 8) * 72 + kk * 8 + 4 + tig];
    }
    __syncthreads();

    float acc_o[8][4] = {};
    float m0v = -1e30f, m1v = -1e30f, l0 = 0.0f, l1 = 0.0f;

    int tt64 = tt * 2 + (lrow >= 64 ? 1 : 0);
    int rloc = lrow & 63;
    int nst = 2 * tt + 2;

    flash_load_kv(dynsm, dynsm + 4608, kb, vb, 0, tid);

    for (int st = 0; st < nst; st++) {
        int s = st & 1;
        float* Ks = dynsm + s * 9216;
        float* Vs = Ks + 4608;
        if (st + 1 < nst) {
            float* Kn = dynsm + (s ^ 1) * 9216;
            flash_load_kv(Kn, Kn + 4608, kb, vb, (st + 1) * 64, tid);
            cp_wait<1>();
        } else {
            cp_wait<0>();
        }
        __syncthreads();

        // ---- scores = Q @ K^T
        float sc[8][4] = {};
        #pragma unroll
        for (int kk = 0; kk < 8; kk++) {
            #pragma unroll
            for (int j = 0; j < 8; j++) {
                float bf[2];
                bf[0] = Ks[(j * 8 + gid) * 72 + kk * 8 + tig];
                bf[1] = Ks[(j * 8 + gid) * 72 + kk * 8 + 4 + tig];
                mma8(sc[j], qf[kk], bf);
            }
        }

        if (st >= 2 * tt) {   // causal mask
            int s0 = st * 64;
            int rg0 = t0 + lrow, rg1 = rg0 + 8;
            #pragma unroll
            for (int j = 0; j < 8; j++) {
                int cg = s0 + j * 8 + 2 * tig;
                if (cg     > rg0) sc[j][0] = -1e30f;
                if (cg + 1 > rg0) sc[j][1] = -1e30f;
                if (cg     > rg1) sc[j][2] = -1e30f;
                if (cg + 1 > rg1) sc[j][3] = -1e30f;
            }
        }

        // ---- online softmax
        float mx0 = -1e30f, mx1 = -1e30f;
        #pragma unroll
        for (int j = 0; j < 8; j++) {
            mx0 = fmaxf(mx0, fmaxf(sc[j][0], sc[j][1]));
            mx1 = fmaxf(mx1, fmaxf(sc[j][2], sc[j][3]));
        }
        mx0 = fmaxf(mx0, __shfl_xor_sync(0xffffffffu, mx0, 1));
        mx0 = fmaxf(mx0, __shfl_xor_sync(0xffffffffu, mx0, 2));
        mx1 = fmaxf(mx1, __shfl_xor_sync(0xffffffffu, mx1, 1));
        mx1 = fmaxf(mx1, __shfl_xor_sync(0xffffffffu, mx1, 2));

        float mn0 = fmaxf(m0v, mx0), mn1 = fmaxf(m1v, mx1);
        float fac0 = fast_exp(m0v - mn0), fac1 = fast_exp(m1v - mn1);

        float s0v = 0.0f, s1v = 0.0f;
        #pragma unroll
        for (int j = 0; j < 8; j++) {
            sc[j][0] = fast_exp(sc[j][0] - mn0);
            sc[j][1] = fast_exp(sc[j][1] - mn0);
            sc[j][2] = fast_exp(sc[j][2] - mn1);
            sc[j][3] = fast_exp(sc[j][3] - mn1);
            s0v += sc[j][0] + sc[j][1];
            s1v += sc[j][2] + sc[j][3];
        }
        s0v += __shfl_xor_sync(0xffffffffu, s0v, 1);
        s0v += __shfl_xor_sync(0xffffffffu, s0v, 2);
        s1v += __shfl_xor_sync(0xffffffffu, s1v, 1);
        s1v += __shfl_xor_sync(0xffffffffu, s1v, 2);

        l0 = l0 * fac0 + s0v;
        l1 = l1 * fac1 + s1v;
        m0v = mn0; m1v = mn1;

        #pragma unroll
        for (int j = 0; j < 8; j++) {
            acc_o[j][0] *= fac0; acc_o[j][1] *= fac0;
            acc_o[j][2] *= fac1; acc_o[j][3] *= fac1;
        }

        // ---- side outputs straight from fragments
        __half* tb = g_e + ((size_t)(bh * NT + tt64) * NT + st) * 4096;
        #pragma unroll
        for (int j = 0; j < 8; j++) {
            int c = j * 8 + 2 * tig;
            *(__half2*)(tb + rloc * 64 + c)       = __floats2half2_rn(sc[j][0], sc[j][1]);
            *(__half2*)(tb + (rloc + 8) * 64 + c) = __floats2half2_rn(sc[j][2], sc[j][3]);
        }
        if (tig == 0) {
            g_mloc[((size_t)bh * T_ + t0 + lrow) * NT + st]     = mn0;
            g_mloc[((size_t)bh * T_ + t0 + lrow + 8) * NT + st] = mn1;
        }

        // ---- O += P @ V (shuffle relayout, no smem)
        int src0 = (lane & ~3) | (tig >> 1);
        int src2 = src0 + 2;
        bool odd = tig & 1;
        #pragma unroll
        for (int kk = 0; kk < 8; kk++) {
            float e00 = __shfl_sync(0xffffffffu, sc[kk][0], src0);
            float e01 = __shfl_sync(0xffffffffu, sc[kk][1], src0);
            float e10 = __shfl_sync(0xffffffffu, sc[kk][2], src0);
            float e11 = __shfl_sync(0xffffffffu, sc[kk][3], src0);
            float f00 = __shfl_sync(0xffffffffu, sc[kk][0], src2);
            float f01 = __shfl_sync(0xffffffffu, sc[kk][1], src2);
            float f10 = __shfl_sync(0xffffffffu, sc[kk][2], src2);
            float f11 = __shfl_sync(0xffffffffu, sc[kk][3], src2);
            float pf[4];
            pf[0] = to_tf32(odd ? e01 : e00);
            pf[1] = to_tf32(odd ? e11 : e10);
            pf[2] = to_tf32(odd ? f01 : f00);
            pf[3] = to_tf32(odd ? f11 : f10);
            #pragma unroll
            for (int j = 0; j < 8; j++) {
                float bf[2];
                bf[0] = Vs[(kk * 8 + tig) * 72 + j * 8 + gid];
                bf[1] = Vs[(kk * 8 + 4 + tig) * 72 + j * 8 + gid];
                mma8(acc_o[j], pf, bf);
            }
        }
        __syncthreads();
    }

    // ---- epilogue (rounded for outproj consumption)
    int b = bh >> 4, h = bh & 15;
    float inv0 = 1.0f / l0, inv1 = 1.0f / l1;
    #pragma unroll
    for (int j = 0; j < 8; j++) {
        int d = h * 64 + j * 8 + 2 * tig;
        float2 v0 = { to_tf32(acc_o[j][0] * inv0), to_tf32(acc_o[j][1] * inv0) };
        float2 v1 = { to_tf32(acc_o[j][2] * inv1), to_tf32(acc_o[j][3] * inv1) };
        *(float2*)&g_attn[((size_t)(t0 + lrow) * B_ + b) * D_ + d] = v0;
        *(float2*)&g_attn[((size_t)(t0 + lrow + 8) * B_ + b) * D_ + d] = v1;
    }
    if (tig == 0) {
        g_lse[(size_t)bh * T_ + t0 + lrow]     = m0v + logf(l0);
        g_lse[(size_t)bh * T_ + t0 + lrow + 8] = m1v + logf(l1);
    }
}

// ---------------------------------------------------------------------------
// Avg weights: out[b,t,s] = (1/H) * sum_h e[bh,t,s] * exp(m_loc - lse).
// ---------------------------------------------------------------------------
__global__ __launch_bounds__(256) void avg_kernel(float* __restrict__ out)
{
    __shared__ float sfac[64];
    int st = blockIdx.x, tt = blockIdx.y, b = blockIdx.z;
    int t0 = tt * 64, s0 = st * 64;
    int tid = threadIdx.x;
    int row = tid >> 2, cseg = (tid & 3) * 16;

    float* dst = out + (size_t)ROWS * D_ + (size_t)b * T_ * T_;
    float4* pout = (float4*)(dst + (size_t)(t0 + row) * T_ + s0 + cseg);

    if (st > tt) {
        float4 z = {0.f, 0.f, 0.f, 0.f};
        pout[0] = z; pout[1] = z; pout[2] = z; pout[3] = z;
        return;
    }

    float acc[16] = {};
    for (int h = 0; h < H_; h++) {
        int bh = b * H_ + h;
        __syncthreads();
        if (tid < 64) {
            float ml = g_mloc[((size_t)bh * T_ + t0 + tid) * NT + st];
            float ls = g_lse[(size_t)bh * T_ + t0 + tid];
            sfac[tid] = fast_exp(ml - ls);
        }
        __syncthreads();
        float fac = sfac[row];
        const uint4* ep = (const uint4*)(g_e + ((size_t)(bh * NT + tt) * NT + st) * 4096
                                         + row * 64 + cseg);
        #pragma unroll
        for (int q2 = 0; q2 < 2; q2++) {
            uint4 u = ep[q2];
            const __half2* hp = (const __half2*)&u;
            #pragma unroll
            for (int i = 0; i < 4; i++) {
                float2 f = __half22float2(hp[i]);
                acc[q2 * 8 + i * 2]     += fac * f.x;
                acc[q2 * 8 + i * 2 + 1] += fac * f.y;
            }
        }
    }
    const float invH = 1.0f / (float)H_;
    #pragma unroll
    for (int q2 = 0; q2 < 4; q2++) {
        float4 v = { acc[q2 * 4] * invH, acc[q2 * 4 + 1] * invH,
                     acc[q2 * 4 + 2] * invH, acc[q2 * 4 + 3] * invH };
        pout[q2] = v;
    }
}

// ---------------------------------------------------------------------------
extern "C" void kernel_launch(void* const* d_in, const int* in_sizes, int n_in,
                              void* d_out, int out_size)
{
    const float* query = (const float*)d_in[0];
    const float* qw = (const float*)d_in[1];
    const float* qb = (const float*)d_in[2];
    const float* kw = (const float*)d_in[3];
    const float* kb = (const float*)d_in[4];
    const float* vw = (const float*)d_in[5];
    const float* vb = (const float*)d_in[6];
    const float* ow = (const float*)d_in[7];
    const float* ob = (const float*)d_in[8];
    float* out = (float*)d_out;

    const int SM = 73728;   // 2-stage smem for gemm & flash
    static bool attr_done = false;
    cudaFuncSetAttribute(gemm_tf32, cudaFuncAttributeMaxDynamicSharedMemorySize, SM);
    cudaFuncSetAttribute(flash_tf32, cudaFuncAttributeMaxDynamicSharedMemorySize, SM);
    (void)attr_done;

    // 0) tf32-round inputs/weights once
    prep_round<<<8192, 256>>>(query, qw, kw, vw, ow);

    // 1) fused Q/K/V projections
    gemm_tf32<<<dim3(8, 32, 3), 256, SM>>>(qb, kb, vb, nullptr, -1);

    // 2) flash attention
    flash_tf32<<<dim3(NQT, BH), 256, SM>>>();

    // 3) averaged attention weights
    avg_kernel<<<dim3(NT, NT, B_), 256>>>(out);

    // 4) output projection
    gemm_tf32<<<dim3(8, 32, 1), 256, SM>>>(ob, ob, ob, out, 3);
}

// round 5
// speedup vs baseline: 6.0760x; 1.6594x over previous
#include <cuda_runtime.h>
#include <cuda_fp16.h>
#include <math.h>
#include <stdint.h>

#define T_  2048
#define B_  2
#define D_  1024
#define H_  16
#define HD  64
#define ROWS (T_*B_)   // 4096
#define BH  (B_*H_)    // 32
#define NT  (T_/64)    // 32 (64-col score tiles)
#define NQT (T_/128)   // 16 (128-row q blocks)
#define SCALING 0.125f

// ---------------- scratch (static device globals) ---------------------------
__device__ __half g_x [ROWS * D_];             // fp16 input
__device__ __half g_wq[D_ * D_], g_wk[D_ * D_], g_wv[D_ * D_], g_wo[D_ * D_];
__device__ __half g_qh[BH * T_ * HD];          // [bh][t][d]
__device__ __half g_kh[BH * T_ * HD];          // [bh][t][d]
__device__ __half g_vt[BH * HD * T_];          // [bh][d][t]  (transposed V)
__device__ __half g_attn[ROWS * D_];           // [t*B+b][h*64+d]
__device__ float  g_lse [BH * T_];
__device__ float  g_mloc[BH * T_ * NT];
__device__ __half g_e[(size_t)BH * T_ * T_];

// ---------------- helpers ---------------------------------------------------
__device__ __forceinline__ void mma16(float c[4], const unsigned a[4], const unsigned b[2]) {
    asm volatile(
        "mma.sync.aligned.m16n8k16.row.col.f32.f16.f16.f32 "
        "{%0,%1,%2,%3},{%4,%5,%6,%7},{%8,%9},{%0,%1,%2,%3};"
        : "+f"(c[0]), "+f"(c[1]), "+f"(c[2]), "+f"(c[3])
        : "r"(a[0]), "r"(a[1]), "r"(a[2]), "r"(a[3]), "r"(b[0]), "r"(b[1]));
}

__device__ __forceinline__ void cp16(const void* dst_smem, const void* src) {
    uint32_t d = (uint32_t)__cvta_generic_to_shared(dst_smem);
    asm volatile("cp.async.cg.shared.global [%0], [%1], 16;" :: "r"(d), "l"(src));
}
#define CP_COMMIT() asm volatile("cp.async.commit_group;")
template<int N> __device__ __forceinline__ void cp_wait() {
    asm volatile("cp.async.wait_group %0;" :: "n"(N));
}

// exp(x) for x <= ~0, FMA-pipe only
__device__ __forceinline__ float fast_exp(float x) {
    const float L = 1.4426950408889634f;
    x = fmaxf(x, -80.0f);
    float t = fmaf(x, L, 12582912.0f);
    int   i = __float_as_int(t) - 0x4B400000;
    float k = t - 12582912.0f;
    float f = fmaf(x, L, -k);
    float p = 1.3333558146e-3f;
    p = fmaf(p, f, 9.6181291076e-3f);
    p = fmaf(p, f, 5.5504108664e-2f);
    p = fmaf(p, f, 2.4022650696e-1f);
    p = fmaf(p, f, 6.9314718056e-1f);
    p = fmaf(p, f, 1.0f);
    return __int_as_float(__float_as_int(p) + (i << 23));
}

// ---------------------------------------------------------------------------
// Prep: fp16-convert query + weights into scratch (float4 -> 4 halfs).
// ---------------------------------------------------------------------------
__global__ __launch_bounds__(256) void prep_half(
    const float* __restrict__ q,  const float* __restrict__ wq,
    const float* __restrict__ wk, const float* __restrict__ wv,
    const float* __restrict__ wo)
{
    const size_t NX = (size_t)ROWS * D_ / 4;
    const size_t NW = (size_t)D_ * D_ / 4;
    size_t i = (size_t)blockIdx.x * 256 + threadIdx.x;
    const float* src; __half* dst; size_t off;
    if      (i < NX)        { src = q;  dst = g_x;  off = i; }
    else if (i < NX + NW)   { src = wq; dst = g_wq; off = i - NX; }
    else if (i < NX + 2*NW) { src = wk; dst = g_wk; off = i - NX - NW; }
    else if (i < NX + 3*NW) { src = wv; dst = g_wv; off = i - NX - 2*NW; }
    else                    { src = wo; dst = g_wo; off = i - NX - 3*NW; }
    float4 v = ((const float4*)src)[off];
    __half2 h0 = __floats2half2_rn(v.x, v.y);
    __half2 h1 = __floats2half2_rn(v.z, v.w);
    uint2 u = { *(unsigned*)&h0, *(unsigned*)&h1 };
    ((uint2*)dst)[off] = u;
}

// ---------------------------------------------------------------------------
// GEMM (fp16 m16n8k16, cp.async 2-stage): C[4096x1024] = A @ W^T + bias.
// modes 0/1: -> g_qh/g_kh [bh][t][d] (q scaled). mode 2: -> g_vt [bh][d][t].
// mode 3: A = g_attn, W = g_wo -> final fp32 out.
// Dyn smem: 2 stages x (A 128x40h + W 128x40h) = 40,960 B.
// ---------------------------------------------------------------------------
extern __shared__ __half dynh[];

__device__ __forceinline__ void gemm_load_tile(
    __half* AsS, __half* WsS, const __half* Ain, const __half* W,
    int m0, int n0, int k0, int tid)
{
    #pragma unroll
    for (int p = 0; p < 2; p++) {
        int i = p * 256 + tid;            // 512 chunks of 8 halfs per matrix
        int row = i >> 2, c = (i & 3) * 8;
        cp16(AsS + row * 40 + c, Ain + (size_t)(m0 + row) * D_ + k0 + c);
        cp16(WsS + row * 40 + c, W   + (size_t)(n0 + row) * D_ + k0 + c);
    }
    CP_COMMIT();
}

__global__ __launch_bounds__(256) void gemm_fp16(
    const float* __restrict__ Bi0, const float* __restrict__ Bi1,
    const float* __restrict__ Bi2, float* __restrict__ C, int modeSel)
{
    int mode = (modeSel < 0) ? (int)blockIdx.z : modeSel;
    const __half* W    = (mode == 1) ? g_wk : (mode == 2) ? g_wv : (mode == 3) ? g_wo : g_wq;
    const float* bias  = (mode == 1) ? Bi1 : (mode == 2) ? Bi2 : Bi0;
    const __half* Ain  = (mode == 3) ? g_attn : g_x;

    int m0 = blockIdx.y * 128;
    int n0 = blockIdx.x * 128;
    int tid = threadIdx.x, lane = tid & 31, warp = tid >> 5;
    int mw = warp >> 1, nw = warp & 1;
    int gid = lane >> 2, tig = lane & 3;

    float acc[2][8][4] = {};

    gemm_load_tile(dynh, dynh + 5120, Ain, W, m0, n0, 0, tid);

    for (int kt = 0; kt < 32; kt++) {
        int s = kt & 1;
        __half* AsS = dynh + s * 10240;
        __half* WsS = AsS + 5120;
        if (kt + 1 < 32) {
            __half* An = dynh + (s ^ 1) * 10240;
            gemm_load_tile(An, An + 5120, Ain, W, m0, n0, (kt + 1) * 32, tid);
            cp_wait<1>();
        } else {
            cp_wait<0>();
        }
        __syncthreads();

        #pragma unroll
        for (int kc = 0; kc < 2; kc++) {
            unsigned af[2][4];
            #pragma unroll
            for (int mi = 0; mi < 2; mi++) {
                int r = mw * 32 + mi * 16 + gid;
                af[mi][0] = *(const unsigned*)&AsS[r * 40 + kc * 16 + 2 * tig];
                af[mi][1] = *(const unsigned*)&AsS[(r + 8) * 40 + kc * 16 + 2 * tig];
                af[mi][2] = *(const unsigned*)&AsS[r * 40 + kc * 16 + 8 + 2 * tig];
                af[mi][3] = *(const unsigned*)&AsS[(r + 8) * 40 + kc * 16 + 8 + 2 * tig];
            }
            #pragma unroll
            for (int j = 0; j < 8; j++) {
                int n = nw * 64 + j * 8 + gid;
                unsigned bf[2];
                bf[0] = *(const unsigned*)&WsS[n * 40 + kc * 16 + 2 * tig];
                bf[1] = *(const unsigned*)&WsS[n * 40 + kc * 16 + 8 + 2 * tig];
                mma16(acc[0][j], af[0], bf);
                mma16(acc[1][j], af[1], bf);
            }
        }
        __syncthreads();
    }

    #pragma unroll
    for (int mi = 0; mi < 2; mi++) {
        int r = m0 + mw * 32 + mi * 16 + gid;
        #pragma unroll
        for (int j = 0; j < 8; j++) {
            int c = n0 + nw * 64 + j * 8 + tig * 2;
            float b0v = bias[c], b1v = bias[c + 1];
            float2 v0 = { acc[mi][j][0] + b0v, acc[mi][j][1] + b1v };
            float2 v1 = { acc[mi][j][2] + b0v, acc[mi][j][3] + b1v };
            if (mode == 0) { v0.x *= SCALING; v0.y *= SCALING; v1.x *= SCALING; v1.y *= SCALING; }
            if (mode == 3) {
                *(float2*)&C[(size_t)r * D_ + c] = v0;
                *(float2*)&C[(size_t)(r + 8) * D_ + c] = v1;
            } else if (mode == 2) {
                int h = c >> 6, d = c & 63;
                int t = r >> 1, b = r & 1;
                size_t base = ((size_t)(b * H_ + h) * HD + d) * T_;
                g_vt[base + t]      = __float2half(v0.x);
                g_vt[base + T_ + t] = __float2half(v0.y);
                int t8 = t + 4;
                g_vt[base + t8]      = __float2half(v1.x);
                g_vt[base + T_ + t8] = __float2half(v1.y);
            } else {
                __half* outp = (mode == 0) ? g_qh : g_kh;
                int h = c >> 6, d = c & 63;
                int t = r >> 1, b = r & 1;
                __half2 h0 = __floats2half2_rn(v0.x, v0.y);
                __half2 h1 = __floats2half2_rn(v1.x, v1.y);
                *(__half2*)&outp[((size_t)(b * H_ + h) * T_ + t) * HD + d] = h0;
                *(__half2*)&outp[((size_t)(b * H_ + h) * T_ + t + 4) * HD + d] = h1;
            }
        }
    }
}

// ---------------------------------------------------------------------------
// Flash attention (fp16 m16n8k16, cp.async 2-stage K/V): 128 q-rows per block.
// P fragments feed PV mma directly (C->A fragment identity for fp16 k16).
// Dyn smem: 4 buffers x 64x72 halfs = 36,864 B (Q staged there first).
// ---------------------------------------------------------------------------
__device__ __forceinline__ void flash_load_kv(
    __half* Kst, __half* Vst, const __half* kb, const __half* vtb, int s0, int tid)
{
    #pragma unroll
    for (int p = 0; p < 2; p++) {
        int i = p * 256 + tid;            // 512 chunks of 8 halfs each matrix
        int row = i >> 3, c = (i & 7) * 8;
        cp16(Kst + row * 72 + c, kb  + (size_t)(s0 + row) * HD + c);   // K [s][d]
        cp16(Vst + row * 72 + c, vtb + (size_t)row * T_ + s0 + c);     // V^T [d][s]
    }
    CP_COMMIT();
}

__global__ __launch_bounds__(256) void flash_fp16()
{
    int bh = blockIdx.y;
    int tt = (int)(gridDim.x - 1 - blockIdx.x);   // heavy blocks first
    int t0 = tt * 128;
    int tid = threadIdx.x, lane = tid & 31, w = tid >> 5;
    int gid = lane >> 2, tig = lane & 3;
    int lrow = w * 16 + gid;

    const __half* qb  = g_qh + (size_t)bh * T_ * HD;
    const __half* kb  = g_kh + (size_t)bh * T_ * HD;
    const __half* vtb = g_vt + (size_t)bh * HD * T_;

    // ---- stage Q (128x64 halfs) through smem, pull A-fragments
    {
        #pragma unroll
        for (int p = 0; p < 4; p++) {
            int i = p * 256 + tid;
            int row = i >> 3, c = (i & 7) * 8;
            uint4 v = *(const uint4*)(qb + (size_t)(t0 + row) * HD + c);
            *(uint4*)(dynh + row * 72 + c) = v;
        }
    }
    __syncthreads();
    unsigned qf[4][4];
    #pragma unroll
    for (int kk = 0; kk < 4; kk++) {
        qf[kk][0] = *(const unsigned*)&dynh[lrow * 72 + kk * 16 + 2 * tig];
        qf[kk][1] = *(const unsigned*)&dynh[(lrow + 8) * 72 + kk * 16 + 2 * tig];
        qf[kk][2] = *(const unsigned*)&dynh[lrow * 72 + kk * 16 + 8 + 2 * tig];
        qf[kk][3] = *(const unsigned*)&dynh[(lrow + 8) * 72 + kk * 16 + 8 + 2 * tig];
    }
    __syncthreads();

    float acc_o[8][4] = {};
    float m0v = -1e30f, m1v = -1e30f, l0 = 0.0f, l1 = 0.0f;

    int tt64 = tt * 2 + (lrow >= 64 ? 1 : 0);
    int rloc = lrow & 63;
    int nst = 2 * tt + 2;

    flash_load_kv(dynh, dynh + 4608, kb, vtb, 0, tid);

    for (int st = 0; st < nst; st++) {
        int s = st & 1;
        __half* Ks = dynh + s * 9216;
        __half* Vs = Ks + 4608;
        if (st + 1 < nst) {
            __half* Kn = dynh + (s ^ 1) * 9216;
            flash_load_kv(Kn, Kn + 4608, kb, vtb, (st + 1) * 64, tid);
            cp_wait<1>();
        } else {
            cp_wait<0>();
        }
        __syncthreads();

        // ---- scores = Q @ K^T  (fp16 k16)
        float sc[8][4] = {};
        #pragma unroll
        for (int kk = 0; kk < 4; kk++) {
            #pragma unroll
            for (int j = 0; j < 8; j++) {
                unsigned bf[2];
                bf[0] = *(const unsigned*)&Ks[(j * 8 + gid) * 72 + kk * 16 + 2 * tig];
                bf[1] = *(const unsigned*)&Ks[(j * 8 + gid) * 72 + kk * 16 + 8 + 2 * tig];
                mma16(sc[j], qf[kk], bf);
            }
        }

        if (st >= 2 * tt) {   // causal mask
            int s0 = st * 64;
            int rg0 = t0 + lrow, rg1 = rg0 + 8;
            #pragma unroll
            for (int j = 0; j < 8; j++) {
                int cg = s0 + j * 8 + 2 * tig;
                if (cg     > rg0) sc[j][0] = -1e30f;
                if (cg + 1 > rg0) sc[j][1] = -1e30f;
                if (cg     > rg1) sc[j][2] = -1e30f;
                if (cg + 1 > rg1) sc[j][3] = -1e30f;
            }
        }

        // ---- online softmax
        float mx0 = -1e30f, mx1 = -1e30f;
        #pragma unroll
        for (int j = 0; j < 8; j++) {
            mx0 = fmaxf(mx0, fmaxf(sc[j][0], sc[j][1]));
            mx1 = fmaxf(mx1, fmaxf(sc[j][2], sc[j][3]));
        }
        mx0 = fmaxf(mx0, __shfl_xor_sync(0xffffffffu, mx0, 1));
        mx0 = fmaxf(mx0, __shfl_xor_sync(0xffffffffu, mx0, 2));
        mx1 = fmaxf(mx1, __shfl_xor_sync(0xffffffffu, mx1, 1));
        mx1 = fmaxf(mx1, __shfl_xor_sync(0xffffffffu, mx1, 2));

        float mn0 = fmaxf(m0v, mx0), mn1 = fmaxf(m1v, mx1);
        float fac0 = fast_exp(m0v - mn0), fac1 = fast_exp(m1v - mn1);

        float s0v = 0.0f, s1v = 0.0f;
        #pragma unroll
        for (int j = 0; j < 8; j++) {
            sc[j][0] = fast_exp(sc[j][0] - mn0);
            sc[j][1] = fast_exp(sc[j][1] - mn0);
            sc[j][2] = fast_exp(sc[j][2] - mn1);
            sc[j][3] = fast_exp(sc[j][3] - mn1);
            s0v += sc[j][0] + sc[j][1];
            s1v += sc[j][2] + sc[j][3];
        }
        s0v += __shfl_xor_sync(0xffffffffu, s0v, 1);
        s0v += __shfl_xor_sync(0xffffffffu, s0v, 2);
        s1v += __shfl_xor_sync(0xffffffffu, s1v, 1);
        s1v += __shfl_xor_sync(0xffffffffu, s1v, 2);

        l0 = l0 * fac0 + s0v;
        l1 = l1 * fac1 + s1v;
        m0v = mn0; m1v = mn1;

        #pragma unroll
        for (int j = 0; j < 8; j++) {
            acc_o[j][0] *= fac0; acc_o[j][1] *= fac0;
            acc_o[j][2] *= fac1; acc_o[j][3] *= fac1;
        }

        // ---- pack P to half2 (PV A-fragments == g_e store values)
        unsigned p0[8], p1[8];
        #pragma unroll
        for (int j = 0; j < 8; j++) {
            __half2 a = __floats2half2_rn(sc[j][0], sc[j][1]);
            __half2 b2 = __floats2half2_rn(sc[j][2], sc[j][3]);
            p0[j] = *(unsigned*)&a;
            p1[j] = *(unsigned*)&b2;
        }

        __half* tb = g_e + ((size_t)(bh * NT + tt64) * NT + st) * 4096;
        #pragma unroll
        for (int j = 0; j < 8; j++) {
            int c = j * 8 + 2 * tig;
            *(unsigned*)(tb + rloc * 64 + c)       = p0[j];
            *(unsigned*)(tb + (rloc + 8) * 64 + c) = p1[j];
        }
        if (tig == 0) {
            g_mloc[((size_t)bh * T_ + t0 + lrow) * NT + st]     = mn0;
            g_mloc[((size_t)bh * T_ + t0 + lrow + 8) * NT + st] = mn1;
        }

        // ---- O += P @ V  (A = P fragments directly, B = V^T half2 loads)
        #pragma unroll
        for (int kk = 0; kk < 4; kk++) {
            unsigned af[4] = { p0[2 * kk], p1[2 * kk], p0[2 * kk + 1], p1[2 * kk + 1] };
            #pragma unroll
            for (int j = 0; j < 8; j++) {
                unsigned bf[2];
                bf[0] = *(const unsigned*)&Vs[(j * 8 + gid) * 72 + kk * 16 + 2 * tig];
                bf[1] = *(const unsigned*)&Vs[(j * 8 + gid) * 72 + kk * 16 + 8 + 2 * tig];
                mma16(acc_o[j], af, bf);
            }
        }
        __syncthreads();
    }

    // ---- epilogue: fp16 attn for outproj
    int b = bh >> 4, h = bh & 15;
    float inv0 = 1.0f / l0, inv1 = 1.0f / l1;
    #pragma unroll
    for (int j = 0; j < 8; j++) {
        int d = h * 64 + j * 8 + 2 * tig;
        __half2 h0 = __floats2half2_rn(acc_o[j][0] * inv0, acc_o[j][1] * inv0);
        __half2 h1 = __floats2half2_rn(acc_o[j][2] * inv1, acc_o[j][3] * inv1);
        *(__half2*)&g_attn[((size_t)(t0 + lrow) * B_ + b) * D_ + d] = h0;
        *(__half2*)&g_attn[((size_t)(t0 + lrow + 8) * B_ + b) * D_ + d] = h1;
    }
    if (tig == 0) {
        g_lse[(size_t)bh * T_ + t0 + lrow]     = m0v + logf(l0);
        g_lse[(size_t)bh * T_ + t0 + lrow + 8] = m1v + logf(l1);
    }
}

// ---------------------------------------------------------------------------
// Avg weights: out[b,t,s] = (1/H) * sum_h e[bh,t,s] * exp(m_loc - lse).
// ---------------------------------------------------------------------------
__global__ __launch_bounds__(256) void avg_kernel(float* __restrict__ out)
{
    __shared__ float sfac[64];
    int st = blockIdx.x, tt = blockIdx.y, b = blockIdx.z;
    int t0 = tt * 64, s0 = st * 64;
    int tid = threadIdx.x;
    int row = tid >> 2, cseg = (tid & 3) * 16;

    float* dst = out + (size_t)ROWS * D_ + (size_t)b * T_ * T_;
    float4* pout = (float4*)(dst + (size_t)(t0 + row) * T_ + s0 + cseg);

    if (st > tt) {
        float4 z = {0.f, 0.f, 0.f, 0.f};
        pout[0] = z; pout[1] = z; pout[2] = z; pout[3] = z;
        return;
    }

    float acc[16] = {};
    for (int h = 0; h < H_; h++) {
        int bh = b * H_ + h;
        __syncthreads();
        if (tid < 64) {
            float ml = g_mloc[((size_t)bh * T_ + t0 + tid) * NT + st];
            float ls = g_lse[(size_t)bh * T_ + t0 + tid];
            sfac[tid] = fast_exp(ml - ls);
        }
        __syncthreads();
        float fac = sfac[row];
        const uint4* ep = (const uint4*)(g_e + ((size_t)(bh * NT + tt) * NT + st) * 4096
                                         + row * 64 + cseg);
        #pragma unroll
        for (int q2 = 0; q2 < 2; q2++) {
            uint4 u = ep[q2];
            const __half2* hp = (const __half2*)&u;
            #pragma unroll
            for (int i = 0; i < 4; i++) {
                float2 f = __half22float2(hp[i]);
                acc[q2 * 8 + i * 2]     += fac * f.x;
                acc[q2 * 8 + i * 2 + 1] += fac * f.y;
            }
        }
    }
    const float invH = 1.0f / (float)H_;
    #pragma unroll
    for (int q2 = 0; q2 < 4; q2++) {
        float4 v = { acc[q2 * 4] * invH, acc[q2 * 4 + 1] * invH,
                     acc[q2 * 4 + 2] * invH, acc[q2 * 4 + 3] * invH };
        pout[q2] = v;
    }
}

// ---------------------------------------------------------------------------
extern "C" void kernel_launch(void* const* d_in, const int* in_sizes, int n_in,
                              void* d_out, int out_size)
{
    const float* query = (const float*)d_in[0];
    const float* qw = (const float*)d_in[1];
    const float* qb = (const float*)d_in[2];
    const float* kw = (const float*)d_in[3];
    const float* kb = (const float*)d_in[4];
    const float* vw = (const float*)d_in[5];
    const float* vb = (const float*)d_in[6];
    const float* ow = (const float*)d_in[7];
    const float* ob = (const float*)d_in[8];
    float* out = (float*)d_out;

    const int SM_G = 40960;   // gemm: 2 stages x (A+W) fp16
    const int SM_F = 36864;   // flash: 2 stages x (K+V^T) fp16
    cudaFuncSetAttribute(gemm_fp16, cudaFuncAttributeMaxDynamicSharedMemorySize, SM_G);
    cudaFuncSetAttribute(flash_fp16, cudaFuncAttributeMaxDynamicSharedMemorySize, SM_F);

    // 0) fp16-convert inputs/weights once
    prep_half<<<8192, 256>>>(query, qw, kw, vw, ow);

    // 1) fused Q/K/V projections
    gemm_fp16<<<dim3(8, 32, 3), 256, SM_G>>>(qb, kb, vb, nullptr, -1);

    // 2) flash attention
    flash_fp16<<<dim3(NQT, BH), 256, SM_F>>>();

    // 3) averaged attention weights
    avg_kernel<<<dim3(NT, NT, B_), 256>>>(out);

    // 4) output projection
    gemm_fp16<<<dim3(8, 32, 1), 256, SM_G>>>(ob, ob, ob, out, 3);
}

// round 6
// speedup vs baseline: 6.5187x; 1.0729x over previous
#include <cuda_runtime.h>
#include <cuda_fp16.h>
#include <math.h>
#include <stdint.h>

#define T_  2048
#define B_  2
#define D_  1024
#define H_  16
#define HD  64
#define ROWS (T_*B_)   // 4096
#define BH  (B_*H_)    // 32
#define NT  (T_/64)    // 32 (64-col score tiles)
#define NQT (T_/128)   // 16 (128-row q blocks)
#define SCALING 0.125f

// ---------------- scratch (static device globals) ---------------------------
__device__ __half g_x [ROWS * D_];
__device__ __half g_wq[D_ * D_], g_wk[D_ * D_], g_wv[D_ * D_], g_wo[D_ * D_];
__device__ __half g_qh[BH * T_ * HD];          // [bh][t][d]
__device__ __half g_kh[BH * T_ * HD];          // [bh][t][d]
__device__ __half g_vt[BH * HD * T_];          // [bh][d][t]
__device__ __half g_attn[ROWS * D_];
__device__ float  g_lse [BH * T_];
__device__ float  g_mloc[BH * T_ * NT];
__device__ __half g_e[(size_t)BH * T_ * T_];

// ---------------- helpers ---------------------------------------------------
__device__ __forceinline__ void mma16(float c[4], const unsigned a[4], const unsigned b[2]) {
    asm volatile(
        "mma.sync.aligned.m16n8k16.row.col.f32.f16.f16.f32 "
        "{%0,%1,%2,%3},{%4,%5,%6,%7},{%8,%9},{%0,%1,%2,%3};"
        : "+f"(c[0]), "+f"(c[1]), "+f"(c[2]), "+f"(c[3])
        : "r"(a[0]), "r"(a[1]), "r"(a[2]), "r"(a[3]), "r"(b[0]), "r"(b[1]));
}

__device__ __forceinline__ void ldm_x4(unsigned r[4], uint32_t addr) {
    asm volatile("ldmatrix.sync.aligned.m8n8.x4.shared.b16 {%0,%1,%2,%3}, [%4];"
        : "=r"(r[0]), "=r"(r[1]), "=r"(r[2]), "=r"(r[3]) : "r"(addr));
}

__device__ __forceinline__ uint32_t sptr(const void* p) {
    return (uint32_t)__cvta_generic_to_shared(p);
}

__device__ __forceinline__ void cp16(const void* dst_smem, const void* src) {
    uint32_t d = (uint32_t)__cvta_generic_to_shared(dst_smem);
    asm volatile("cp.async.cg.shared.global [%0], [%1], 16;" :: "r"(d), "l"(src));
}
#define CP_COMMIT() asm volatile("cp.async.commit_group;")
template<int N> __device__ __forceinline__ void cp_wait() {
    asm volatile("cp.async.wait_group %0;" :: "n"(N));
}

// exp(x) for x <= ~0, FMA-pipe only
__device__ __forceinline__ float fast_exp(float x) {
    const float L = 1.4426950408889634f;
    x = fmaxf(x, -80.0f);
    float t = fmaf(x, L, 12582912.0f);
    int   i = __float_as_int(t) - 0x4B400000;
    float k = t - 12582912.0f;
    float f = fmaf(x, L, -k);
    float p = 1.3333558146e-3f;
    p = fmaf(p, f, 9.6181291076e-3f);
    p = fmaf(p, f, 5.5504108664e-2f);
    p = fmaf(p, f, 2.4022650696e-1f);
    p = fmaf(p, f, 6.9314718056e-1f);
    p = fmaf(p, f, 1.0f);
    return __int_as_float(__float_as_int(p) + (i << 23));
}

// ---------------------------------------------------------------------------
// Prep: fp16-convert query + weights.
// ---------------------------------------------------------------------------
__global__ __launch_bounds__(256) void prep_half(
    const float* __restrict__ q,  const float* __restrict__ wq,
    const float* __restrict__ wk, const float* __restrict__ wv,
    const float* __restrict__ wo)
{
    const size_t NX = (size_t)ROWS * D_ / 4;
    const size_t NW = (size_t)D_ * D_ / 4;
    size_t i = (size_t)blockIdx.x * 256 + threadIdx.x;
    const float* src; __half* dst; size_t off;
    if      (i < NX)        { src = q;  dst = g_x;  off = i; }
    else if (i < NX + NW)   { src = wq; dst = g_wq; off = i - NX; }
    else if (i < NX + 2*NW) { src = wk; dst = g_wk; off = i - NX - NW; }
    else if (i < NX + 3*NW) { src = wv; dst = g_wv; off = i - NX - 2*NW; }
    else                    { src = wo; dst = g_wo; off = i - NX - 3*NW; }
    float4 v = ((const float4*)src)[off];
    __half2 h0 = __floats2half2_rn(v.x, v.y);
    __half2 h1 = __floats2half2_rn(v.z, v.w);
    uint2 u = { *(unsigned*)&h0, *(unsigned*)&h1 };
    ((uint2*)dst)[off] = u;
}

// ---------------------------------------------------------------------------
// GEMM (fp16 m16n8k16 + ldmatrix, cp.async 2-stage).
// ---------------------------------------------------------------------------
extern __shared__ __half dynh[];

__device__ __forceinline__ void gemm_load_tile(
    __half* AsS, __half* WsS, const __half* Ain, const __half* W,
    int m0, int n0, int k0, int tid)
{
    #pragma unroll
    for (int p = 0; p < 2; p++) {
        int i = p * 256 + tid;
        int row = i >> 2, c = (i & 3) * 8;
        cp16(AsS + row * 40 + c, Ain + (size_t)(m0 + row) * D_ + k0 + c);
        cp16(WsS + row * 40 + c, W   + (size_t)(n0 + row) * D_ + k0 + c);
    }
    CP_COMMIT();
}

__global__ __launch_bounds__(256) void gemm_fp16(
    const float* __restrict__ Bi0, const float* __restrict__ Bi1,
    const float* __restrict__ Bi2, float* __restrict__ C, int modeSel)
{
    int mode = (modeSel < 0) ? (int)blockIdx.z : modeSel;
    const __half* W    = (mode == 1) ? g_wk : (mode == 2) ? g_wv : (mode == 3) ? g_wo : g_wq;
    const float* bias  = (mode == 1) ? Bi1 : (mode == 2) ? Bi2 : Bi0;
    const __half* Ain  = (mode == 3) ? g_attn : g_x;

    int m0 = blockIdx.y * 128;
    int n0 = blockIdx.x * 128;
    int tid = threadIdx.x, lane = tid & 31, warp = tid >> 5;
    int mw = warp >> 1, nw = warp & 1;
    int gid = lane >> 2, tig = lane & 3;

    // ldmatrix lane mappings
    int a_row = lane & 15;                 // + base row
    int a_col = ((lane >> 4) & 1) * 8;     // + kc*16
    int b_row = ((lane >> 4) & 1) * 8 + (lane & 7);  // + jb*16 (n)
    int b_col = ((lane >> 3) & 1) * 8;     // + kc*16 (k)

    float acc[2][8][4] = {};

    gemm_load_tile(dynh, dynh + 5120, Ain, W, m0, n0, 0, tid);

    for (int kt = 0; kt < 32; kt++) {
        int s = kt & 1;
        __half* AsS = dynh + s * 10240;
        __half* WsS = AsS + 5120;
        if (kt + 1 < 32) {
            __half* An = dynh + (s ^ 1) * 10240;
            gemm_load_tile(An, An + 5120, Ain, W, m0, n0, (kt + 1) * 32, tid);
            cp_wait<1>();
        } else {
            cp_wait<0>();
        }
        __syncthreads();

        #pragma unroll
        for (int kc = 0; kc < 2; kc++) {
            unsigned af[2][4];
            #pragma unroll
            for (int mi = 0; mi < 2; mi++) {
                int r = mw * 32 + mi * 16 + a_row;
                ldm_x4(af[mi], sptr(&AsS[r * 40 + kc * 16 + a_col]));
            }
            #pragma unroll
            for (int jb = 0; jb < 4; jb++) {
                unsigned rr[4];
                int n = nw * 64 + jb * 16 + b_row;
                ldm_x4(rr, sptr(&WsS[n * 40 + kc * 16 + b_col]));
                mma16(acc[0][2 * jb],     af[0], rr);
                mma16(acc[1][2 * jb],     af[1], rr);
                mma16(acc[0][2 * jb + 1], af[0], rr + 2);
                mma16(acc[1][2 * jb + 1], af[1], rr + 2);
            }
        }
        __syncthreads();
    }

    #pragma unroll
    for (int mi = 0; mi < 2; mi++) {
        int r = m0 + mw * 32 + mi * 16 + gid;
        #pragma unroll
        for (int j = 0; j < 8; j++) {
            int c = n0 + nw * 64 + j * 8 + tig * 2;
            float b0v = bias[c], b1v = bias[c + 1];
            float2 v0 = { acc[mi][j][0] + b0v, acc[mi][j][1] + b1v };
            float2 v1 = { acc[mi][j][2] + b0v, acc[mi][j][3] + b1v };
            if (mode == 0) { v0.x *= SCALING; v0.y *= SCALING; v1.x *= SCALING; v1.y *= SCALING; }
            if (mode == 3) {
                *(float2*)&C[(size_t)r * D_ + c] = v0;
                *(float2*)&C[(size_t)(r + 8) * D_ + c] = v1;
            } else if (mode == 2) {
                int h = c >> 6, d = c & 63;
                int t = r >> 1, b = r & 1;
                size_t base = ((size_t)(b * H_ + h) * HD + d) * T_;
                g_vt[base + t]      = __float2half(v0.x);
                g_vt[base + T_ + t] = __float2half(v0.y);
                int t8 = t + 4;
                g_vt[base + t8]      = __float2half(v1.x);
                g_vt[base + T_ + t8] = __float2half(v1.y);
            } else {
                __half* outp = (mode == 0) ? g_qh : g_kh;
                int h = c >> 6, d = c & 63;
                int t = r >> 1, b = r & 1;
                __half2 h0 = __floats2half2_rn(v0.x, v0.y);
                __half2 h1 = __floats2half2_rn(v1.x, v1.y);
                *(__half2*)&outp[((size_t)(b * H_ + h) * T_ + t) * HD + d] = h0;
                *(__half2*)&outp[((size_t)(b * H_ + h) * T_ + t + 4) * HD + d] = h1;
            }
        }
    }
}

// ---------------------------------------------------------------------------
// Flash attention (fp16 m16n8k16 + ldmatrix, cp.async 2-stage K/V).
// ---------------------------------------------------------------------------
__device__ __forceinline__ void flash_load_kv(
    __half* Kst, __half* Vst, const __half* kb, const __half* vtb, int s0, int tid)
{
    #pragma unroll
    for (int p = 0; p < 2; p++) {
        int i = p * 256 + tid;
        int row = i >> 3, c = (i & 7) * 8;
        cp16(Kst + row * 72 + c, kb  + (size_t)(s0 + row) * HD + c);   // K [s][d]
        cp16(Vst + row * 72 + c, vtb + (size_t)row * T_ + s0 + c);     // V^T [d][s]
    }
    CP_COMMIT();
}

__global__ __launch_bounds__(256) void flash_fp16()
{
    int bh = blockIdx.y;
    int tt = (int)(gridDim.x - 1 - blockIdx.x);
    int t0 = tt * 128;
    int tid = threadIdx.x, lane = tid & 31, w = tid >> 5;
    int gid = lane >> 2, tig = lane & 3;
    int lrow = w * 16 + gid;

    int a_row = lane & 15;
    int a_col = ((lane >> 4) & 1) * 8;
    int b_row = ((lane >> 4) & 1) * 8 + (lane & 7);
    int b_col = ((lane >> 3) & 1) * 8;

    const __half* qb  = g_qh + (size_t)bh * T_ * HD;
    const __half* kb  = g_kh + (size_t)bh * T_ * HD;
    const __half* vtb = g_vt + (size_t)bh * HD * T_;

    // ---- stage Q, pull A-fragments via ldmatrix
    {
        #pragma unroll
        for (int p = 0; p < 4; p++) {
            int i = p * 256 + tid;
            int row = i >> 3, c = (i & 7) * 8;
            uint4 v = *(const uint4*)(qb + (size_t)(t0 + row) * HD + c);
            *(uint4*)(dynh + row * 72 + c) = v;
        }
    }
    __syncthreads();
    unsigned qf[4][4];
    {
        int r = w * 16 + a_row;
        #pragma unroll
        for (int kk = 0; kk < 4; kk++)
            ldm_x4(qf[kk], sptr(&dynh[r * 72 + kk * 16 + a_col]));
    }
    __syncthreads();

    float acc_o[8][4] = {};
    float m0v = -1e30f, m1v = -1e30f, l0 = 0.0f, l1 = 0.0f;

    int tt64 = tt * 2 + (lrow >= 64 ? 1 : 0);
    int rloc = lrow & 63;
    int nst = 2 * tt + 2;

    flash_load_kv(dynh, dynh + 4608, kb, vtb, 0, tid);

    for (int st = 0; st < nst; st++) {
        int s = st & 1;
        __half* Ks = dynh + s * 9216;
        __half* Vs = Ks + 4608;
        if (st + 1 < nst) {
            __half* Kn = dynh + (s ^ 1) * 9216;
            flash_load_kv(Kn, Kn + 4608, kb, vtb, (st + 1) * 64, tid);
            cp_wait<1>();
        } else {
            cp_wait<0>();
        }
        __syncthreads();

        // ---- scores = Q @ K^T
        float sc[8][4] = {};
        #pragma unroll
        for (int kk = 0; kk < 4; kk++) {
            #pragma unroll
            for (int jb = 0; jb < 4; jb++) {
                unsigned rr[4];
                int n = jb * 16 + b_row;
                ldm_x4(rr, sptr(&Ks[n * 72 + kk * 16 + b_col]));
                mma16(sc[2 * jb],     qf[kk], rr);
                mma16(sc[2 * jb + 1], qf[kk], rr + 2);
            }
        }

        if (st >= 2 * tt) {   // causal mask
            int s0 = st * 64;
            int rg0 = t0 + lrow, rg1 = rg0 + 8;
            #pragma unroll
            for (int j = 0; j < 8; j++) {
                int cg = s0 + j * 8 + 2 * tig;
                if (cg     > rg0) sc[j][0] = -1e30f;
                if (cg + 1 > rg0) sc[j][1] = -1e30f;
                if (cg     > rg1) sc[j][2] = -1e30f;
                if (cg + 1 > rg1) sc[j][3] = -1e30f;
            }
        }

        // ---- online softmax
        float mx0 = -1e30f, mx1 = -1e30f;
        #pragma unroll
        for (int j = 0; j < 8; j++) {
            mx0 = fmaxf(mx0, fmaxf(sc[j][0], sc[j][1]));
            mx1 = fmaxf(mx1, fmaxf(sc[j][2], sc[j][3]));
        }
        mx0 = fmaxf(mx0, __shfl_xor_sync(0xffffffffu, mx0, 1));
        mx0 = fmaxf(mx0, __shfl_xor_sync(0xffffffffu, mx0, 2));
        mx1 = fmaxf(mx1, __shfl_xor_sync(0xffffffffu, mx1, 1));
        mx1 = fmaxf(mx1, __shfl_xor_sync(0xffffffffu, mx1, 2));

        float mn0 = fmaxf(m0v, mx0), mn1 = fmaxf(m1v, mx1);
        float fac0 = fast_exp(m0v - mn0), fac1 = fast_exp(m1v - mn1);

        float s0v = 0.0f, s1v = 0.0f;
        #pragma unroll
        for (int j = 0; j < 8; j++) {
            sc[j][0] = fast_exp(sc[j][0] - mn0);
            sc[j][1] = fast_exp(sc[j][1] - mn0);
            sc[j][2] = fast_exp(sc[j][2] - mn1);
            sc[j][3] = fast_exp(sc[j][3] - mn1);
            s0v += sc[j][0] + sc[j][1];
            s1v += sc[j][2] + sc[j][3];
        }
        s0v += __shfl_xor_sync(0xffffffffu, s0v, 1);
        s0v += __shfl_xor_sync(0xffffffffu, s0v, 2);
        s1v += __shfl_xor_sync(0xffffffffu, s1v, 1);
        s1v += __shfl_xor_sync(0xffffffffu, s1v, 2);

        l0 = l0 * fac0 + s0v;
        l1 = l1 * fac1 + s1v;
        m0v = mn0; m1v = mn1;

        #pragma unroll
        for (int j = 0; j < 8; j++) {
            acc_o[j][0] *= fac0; acc_o[j][1] *= fac0;
            acc_o[j][2] *= fac1; acc_o[j][3] *= fac1;
        }

        // ---- pack P to half2 (PV A-fragments == g_e store values)
        unsigned p0[8], p1[8];
        #pragma unroll
        for (int j = 0; j < 8; j++) {
            __half2 a = __floats2half2_rn(sc[j][0], sc[j][1]);
            __half2 b2 = __floats2half2_rn(sc[j][2], sc[j][3]);
            p0[j] = *(unsigned*)&a;
            p1[j] = *(unsigned*)&b2;
        }

        __half* tb = g_e + ((size_t)(bh * NT + tt64) * NT + st) * 4096;
        #pragma unroll
        for (int j = 0; j < 8; j++) {
            int c = j * 8 + 2 * tig;
            *(unsigned*)(tb + rloc * 64 + c)       = p0[j];
            *(unsigned*)(tb + (rloc + 8) * 64 + c) = p1[j];
        }
        if (tig == 0) {
            g_mloc[((size_t)bh * T_ + t0 + lrow) * NT + st]     = mn0;
            g_mloc[((size_t)bh * T_ + t0 + lrow + 8) * NT + st] = mn1;
        }

        // ---- O += P @ V
        #pragma unroll
        for (int kk = 0; kk < 4; kk++) {
            unsigned af[4] = { p0[2 * kk], p1[2 * kk], p0[2 * kk + 1], p1[2 * kk + 1] };
            #pragma unroll
            for (int jb = 0; jb < 4; jb++) {
                unsigned rr[4];
                int n = jb * 16 + b_row;
                ldm_x4(rr, sptr(&Vs[n * 72 + kk * 16 + b_col]));
                mma16(acc_o[2 * jb],     af, rr);
                mma16(acc_o[2 * jb + 1], af, rr + 2);
            }
        }
        __syncthreads();
    }

    // ---- epilogue
    int b = bh >> 4, h = bh & 15;
    float inv0 = 1.0f / l0, inv1 = 1.0f / l1;
    #pragma unroll
    for (int j = 0; j < 8; j++) {
        int d = h * 64 + j * 8 + 2 * tig;
        __half2 h0 = __floats2half2_rn(acc_o[j][0] * inv0, acc_o[j][1] * inv0);
        __half2 h1 = __floats2half2_rn(acc_o[j][2] * inv1, acc_o[j][3] * inv1);
        *(__half2*)&g_attn[((size_t)(t0 + lrow) * B_ + b) * D_ + d] = h0;
        *(__half2*)&g_attn[((size_t)(t0 + lrow + 8) * B_ + b) * D_ + d] = h1;
    }
    if (tig == 0) {
        g_lse[(size_t)bh * T_ + t0 + lrow]     = m0v + logf(l0);
        g_lse[(size_t)bh * T_ + t0 + lrow + 8] = m1v + logf(l1);
    }
}

// ---------------------------------------------------------------------------
// Avg weights: out[b,t,s] = (1/H) * sum_h e[bh,t,s] * exp(m_loc - lse).
// ---------------------------------------------------------------------------
__global__ __launch_bounds__(256) void avg_kernel(float* __restrict__ out)
{
    __shared__ float sfac[64];
    int st = blockIdx.x, tt = blockIdx.y, b = blockIdx.z;
    int t0 = tt * 64, s0 = st * 64;
    int tid = threadIdx.x;
    int row = tid >> 2, cseg = (tid & 3) * 16;

    float* dst = out + (size_t)ROWS * D_ + (size_t)b * T_ * T_;
    float4* pout = (float4*)(dst + (size_t)(t0 + row) * T_ + s0 + cseg);

    if (st > tt) {
        float4 z = {0.f, 0.f, 0.f, 0.f};
        pout[0] = z; pout[1] = z; pout[2] = z; pout[3] = z;
        return;
    }

    float acc[16] = {};
    for (int h = 0; h < H_; h++) {
        int bh = b * H_ + h;
        __syncthreads();
        if (tid < 64) {
            float ml = g_mloc[((size_t)bh * T_ + t0 + tid) * NT + st];
            float ls = g_lse[(size_t)bh * T_ + t0 + tid];
            sfac[tid] = fast_exp(ml - ls);
        }
        __syncthreads();
        float fac = sfac[row];
        const uint4* ep = (const uint4*)(g_e + ((size_t)(bh * NT + tt) * NT + st) * 4096
                                         + row * 64 + cseg);
        #pragma unroll
        for (int q2 = 0; q2 < 2; q2++) {
            uint4 u = ep[q2];
            const __half2* hp = (const __half2*)&u;
            #pragma unroll
            for (int i = 0; i < 4; i++) {
                float2 f = __half22float2(hp[i]);
                acc[q2 * 8 + i * 2]     += fac * f.x;
                acc[q2 * 8 + i * 2 + 1] += fac * f.y;
            }
        }
    }
    const float invH = 1.0f / (float)H_;
    #pragma unroll
    for (int q2 = 0; q2 < 4; q2++) {
        float4 v = { acc[q2 * 4] * invH, acc[q2 * 4 + 1] * invH,
                     acc[q2 * 4 + 2] * invH, acc[q2 * 4 + 3] * invH };
        pout[q2] = v;
    }
}

// ---------------------------------------------------------------------------
extern "C" void kernel_launch(void* const* d_in, const int* in_sizes, int n_in,
                              void* d_out, int out_size)
{
    const float* query = (const float*)d_in[0];
    const float* qw = (const float*)d_in[1];
    const float* qb = (const float*)d_in[2];
    const float* kw = (const float*)d_in[3];
    const float* kb = (const float*)d_in[4];
    const float* vw = (const float*)d_in[5];
    const float* vb = (const float*)d_in[6];
    const float* ow = (const float*)d_in[7];
    const float* ob = (const float*)d_in[8];
    float* out = (float*)d_out;

    const int SM_G = 40960;
    const int SM_F = 36864;
    cudaFuncSetAttribute(gemm_fp16, cudaFuncAttributeMaxDynamicSharedMemorySize, SM_G);
    cudaFuncSetAttribute(flash_fp16, cudaFuncAttributeMaxDynamicSharedMemorySize, SM_F);

    prep_half<<<8192, 256>>>(query, qw, kw, vw, ow);
    gemm_fp16<<<dim3(8, 32, 3), 256, SM_G>>>(qb, kb, vb, nullptr, -1);
    flash_fp16<<<dim3(NQT, BH), 256, SM_F>>>();
    avg_kernel<<<dim3(NT, NT, B_), 256>>>(out);
    gemm_fp16<<<dim3(8, 32, 1), 256, SM_G>>>(ob, ob, ob, out, 3);
}

// round 8
// speedup vs baseline: 6.7900x; 1.0416x over previous
#include <cuda_runtime.h>
#include <cuda_fp16.h>
#include <math.h>
#include <stdint.h>

#define T_  2048
#define B_  2
#define D_  1024
#define H_  16
#define HD  64
#define ROWS (T_*B_)   // 4096
#define BH  (B_*H_)    // 32
#define NT  (T_/64)    // 32 (64-col score tiles)
#define NQT (T_/128)   // 16 (128-row q blocks)
#define SCALING 0.125f
#define QSCALE  (0.125f * 1.4426950408889634f)   // fold log2(e) into q

// ---------------- scratch (static device globals) ---------------------------
__device__ __half g_x [ROWS * D_];
__device__ __half g_wq[D_ * D_], g_wk[D_ * D_], g_wv[D_ * D_], g_wo[D_ * D_];
__device__ __half g_qh[BH * T_ * HD];          // [bh][t][d]  (q pre-scaled by QSCALE)
__device__ __half g_kh[BH * T_ * HD];          // [bh][t][d]
__device__ __half g_vt[BH * HD * T_];          // [bh][d][t]
__device__ __half g_attn[ROWS * D_];
__device__ float  g_lse [BH * T_];             // base-2 lse
__device__ float  g_mloc[BH * T_ * NT];        // base-2 running max per s-tile
__device__ __half g_e[(size_t)BH * T_ * T_];

// ---------------- helpers ---------------------------------------------------
__device__ __forceinline__ uint32_t sptr(const void* p) {
    return (uint32_t)__cvta_generic_to_shared(p);
}

__device__ __forceinline__ void cp16(const void* dst_smem, const void* src) {
    uint32_t d = (uint32_t)__cvta_generic_to_shared(dst_smem);
    asm volatile("cp.async.cg.shared.global [%0], [%1], 16;" :: "r"(d), "l"(src));
}
#define CP_COMMIT() asm volatile("cp.async.commit_group;")
template<int N> __device__ __forceinline__ void cp_wait() {
    asm volatile("cp.async.wait_group %0;" :: "n"(N));
}

__device__ __forceinline__ void mma16(float c[4], const unsigned a[4], const unsigned b[2]) {
    asm volatile(
        "mma.sync.aligned.m16n8k16.row.col.f32.f16.f16.f32 "
        "{%0,%1,%2,%3},{%4,%5,%6,%7},{%8,%9},{%0,%1,%2,%3};"
        : "+f"(c[0]), "+f"(c[1]), "+f"(c[2]), "+f"(c[3])
        : "r"(a[0]), "r"(a[1]), "r"(a[2]), "r"(a[3]), "r"(b[0]), "r"(b[1]));
}

__device__ __forceinline__ void ldm_x4(unsigned r[4], uint32_t addr) {
    asm volatile("ldmatrix.sync.aligned.m8n8.x4.shared.b16 {%0,%1,%2,%3}, [%4];"
        : "=r"(r[0]), "=r"(r[1]), "=r"(r[2]), "=r"(r[3]) : "r"(addr));
}

// 2^x for x <= ~0, FMA-pipe only (no MUFU). Input already in log2 domain.
__device__ __forceinline__ float fast_exp2(float x) {
    x = fmaxf(x, -100.0f);
    float t = x + 12582912.0f;                  // round-to-nearest-int magic
    int   i = __float_as_int(t) - 0x4B400000;
    float f = x - (t - 12582912.0f);            // f in [-0.5, 0.5]
    float p = 1.3333558146e-3f;
    p = fmaf(p, f, 9.6181291076e-3f);
    p = fmaf(p, f, 5.5504108664e-2f);
    p = fmaf(p, f, 2.4022650696e-1f);
    p = fmaf(p, f, 6.9314718056e-1f);
    p = fmaf(p, f, 1.0f);
    return __int_as_float(__float_as_int(p) + (i << 23));
}

// ---------------------------------------------------------------------------
// Prep: fp16-convert query + weights.
// ---------------------------------------------------------------------------
__global__ __launch_bounds__(256) void prep_half(
    const float* __restrict__ q,  const float* __restrict__ wq,
    const float* __restrict__ wk, const float* __restrict__ wv,
    const float* __restrict__ wo)
{
    const size_t NX = (size_t)ROWS * D_ / 4;
    const size_t NW = (size_t)D_ * D_ / 4;
    size_t i = (size_t)blockIdx.x * 256 + threadIdx.x;
    const float* src; __half* dst; size_t off;
    if      (i < NX)        { src = q;  dst = g_x;  off = i; }
    else if (i < NX + NW)   { src = wq; dst = g_wq; off = i - NX; }
    else if (i < NX + 2*NW) { src = wk; dst = g_wk; off = i - NX - NW; }
    else if (i < NX + 3*NW) { src = wv; dst = g_wv; off = i - NX - 2*NW; }
    else                    { src = wo; dst = g_wo; off = i - NX - 3*NW; }
    float4 v = ((const float4*)src)[off];
    __half2 h0 = __floats2half2_rn(v.x, v.y);
    __half2 h1 = __floats2half2_rn(v.z, v.w);
    uint2 u = { *(unsigned*)&h0, *(unsigned*)&h1 };
    ((uint2*)dst)[off] = u;
}

// ---------------------------------------------------------------------------
// GEMM (fp16 m16n8k16 + ldmatrix, cp.async 2-stage, BK=64).
// Dyn smem: 2 stages x (A 128x72h + W 128x72h) = 73,728 B.
// ---------------------------------------------------------------------------
extern __shared__ __half dynh[];

__device__ __forceinline__ void gemm_load_stage(
    __half* buf, const __half* Ain, const __half* W,
    int m0, int n0, int k0, int tid)
{
    #pragma unroll
    for (int p = 0; p < 8; p++) {
        int i = p * 256 + tid;            // 0..2047 chunks of 8 halfs
        int which = i >> 10;              // 0 = A, 1 = W
        int j = i & 1023;
        int row = j >> 3, c = (j & 7) * 8;
        const __half* src = which
            ? (W   + (size_t)(n0 + row) * D_ + k0 + c)
            : (Ain + (size_t)(m0 + row) * D_ + k0 + c);
        cp16(buf + which * 9216 + row * 72 + c, src);
    }
    CP_COMMIT();
}

__global__ __launch_bounds__(256) void gemm_fp16(
    const float* __restrict__ Bi0, const float* __restrict__ Bi1,
    const float* __restrict__ Bi2, float* __restrict__ C, int modeSel)
{
    int mode = (modeSel < 0) ? (int)blockIdx.z : modeSel;
    const __half* W    = (mode == 1) ? g_wk : (mode == 2) ? g_wv : (mode == 3) ? g_wo : g_wq;
    const float* bias  = (mode == 1) ? Bi1 : (mode == 2) ? Bi2 : Bi0;
    const __half* Ain  = (mode == 3) ? g_attn : g_x;

    int m0 = blockIdx.y * 128;
    int n0 = blockIdx.x * 128;
    int tid = threadIdx.x, lane = tid & 31, warp = tid >> 5;
    int mw = warp >> 1, nw = warp & 1;
    int gid = lane >> 2, tig = lane & 3;

    int a_row = lane & 15;
    int a_col = ((lane >> 4) & 1) * 8;
    int b_row = ((lane >> 4) & 1) * 8 + (lane & 7);
    int b_col = ((lane >> 3) & 1) * 8;

    float acc[2][8][4] = {};

    gemm_load_stage(dynh, Ain, W, m0, n0, 0, tid);

    for (int kt = 0; kt < 16; kt++) {            // BK = 64
        int s = kt & 1;
        __half* AsS = dynh + s * 18432;
        __half* WsS = AsS + 9216;
        if (kt + 1 < 16) {
            gemm_load_stage(dynh + (s ^ 1) * 18432, Ain, W, m0, n0, (kt + 1) * 64, tid);
            cp_wait<1>();
        } else {
            cp_wait<0>();
        }
        __syncthreads();

        #pragma unroll
        for (int kc = 0; kc < 4; kc++) {
            unsigned af[2][4];
            #pragma unroll
            for (int mi = 0; mi < 2; mi++) {
                int r = mw * 32 + mi * 16 + a_row;
                ldm_x4(af[mi], sptr(&AsS[r * 72 + kc * 16 + a_col]));
            }
            #pragma unroll
            for (int jb = 0; jb < 4; jb++) {
                unsigned rr[4];
                int n = nw * 64 + jb * 16 + b_row;
                ldm_x4(rr, sptr(&WsS[n * 72 + kc * 16 + b_col]));
                mma16(acc[0][2 * jb],     af[0], rr);
                mma16(acc[1][2 * jb],     af[1], rr);
                mma16(acc[0][2 * jb + 1], af[0], rr + 2);
                mma16(acc[1][2 * jb + 1], af[1], rr + 2);
            }
        }
        __syncthreads();
    }

    #pragma unroll
    for (int mi = 0; mi < 2; mi++) {
        int r = m0 + mw * 32 + mi * 16 + gid;
        #pragma unroll
        for (int j = 0; j < 8; j++) {
            int c = n0 + nw * 64 + j * 8 + tig * 2;
            float b0v = bias[c], b1v = bias[c + 1];
            float2 v0 = { acc[mi][j][0] + b0v, acc[mi][j][1] + b1v };
            float2 v1 = { acc[mi][j][2] + b0v, acc[mi][j][3] + b1v };
            if (mode == 0) { v0.x *= QSCALE; v0.y *= QSCALE; v1.x *= QSCALE; v1.y *= QSCALE; }
            if (mode == 3) {
                *(float2*)&C[(size_t)r * D_ + c] = v0;
                *(float2*)&C[(size_t)(r + 8) * D_ + c] = v1;
            } else if (mode == 2) {
                int h = c >> 6, d = c & 63;
                int t = r >> 1, b = r & 1;
                size_t base = ((size_t)(b * H_ + h) * HD + d) * T_;
                g_vt[base + t]      = __float2half(v0.x);
                g_vt[base + T_ + t] = __float2half(v0.y);
                int t8 = t + 4;
                g_vt[base + t8]      = __float2half(v1.x);
                g_vt[base + T_ + t8] = __float2half(v1.y);
            } else {
                __half* outp = (mode == 0) ? g_qh : g_kh;
                int h = c >> 6, d = c & 63;
                int t = r >> 1, b = r & 1;
                __half2 h0 = __floats2half2_rn(v0.x, v0.y);
                __half2 h1 = __floats2half2_rn(v1.x, v1.y);
                *(__half2*)&outp[((size_t)(b * H_ + h) * T_ + t) * HD + d] = h0;
                *(__half2*)&outp[((size_t)(b * H_ + h) * T_ + t + 4) * HD + d] = h1;
            }
        }
    }
}

// ---------------------------------------------------------------------------
// Flash attention (fp16 m16n8k16 + ldmatrix, cp.async 2-stage, base-2 softmax).
// ---------------------------------------------------------------------------
__device__ __forceinline__ void flash_load_kv(
    __half* Kst, __half* Vst, const __half* kb, const __half* vtb, int s0, int tid)
{
    #pragma unroll
    for (int p = 0; p < 2; p++) {
        int i = p * 256 + tid;
        int row = i >> 3, c = (i & 7) * 8;
        cp16(Kst + row * 72 + c, kb  + (size_t)(s0 + row) * HD + c);
        cp16(Vst + row * 72 + c, vtb + (size_t)row * T_ + s0 + c);
    }
    CP_COMMIT();
}

__global__ __launch_bounds__(256) void flash_fp16()
{
    int bh = blockIdx.y;
    int tt = (int)(gridDim.x - 1 - blockIdx.x);
    int t0 = tt * 128;
    int tid = threadIdx.x, lane = tid & 31, w = tid >> 5;
    int gid = lane >> 2, tig = lane & 3;
    int lrow = w * 16 + gid;

    int a_row = lane & 15;
    int a_col = ((lane >> 4) & 1) * 8;
    int b_row = ((lane >> 4) & 1) * 8 + (lane & 7);
    int b_col = ((lane >> 3) & 1) * 8;

    const __half* qb  = g_qh + (size_t)bh * T_ * HD;
    const __half* kb  = g_kh + (size_t)bh * T_ * HD;
    const __half* vtb = g_vt + (size_t)bh * HD * T_;

    {
        #pragma unroll
        for (int p = 0; p < 4; p++) {
            int i = p * 256 + tid;
            int row = i >> 3, c = (i & 7) * 8;
            uint4 v = *(const uint4*)(qb + (size_t)(t0 + row) * HD + c);
            *(uint4*)(dynh + row * 72 + c) = v;
        }
    }
    __syncthreads();
    unsigned qf[4][4];
    {
        int r = w * 16 + a_row;
        #pragma unroll
        for (int kk = 0; kk < 4; kk++)
            ldm_x4(qf[kk], sptr(&dynh[r * 72 + kk * 16 + a_col]));
    }
    __syncthreads();

    float acc_o[8][4] = {};
    float m0v = -1e30f, m1v = -1e30f, l0 = 0.0f, l1 = 0.0f;

    int tt64 = tt * 2 + (lrow >= 64 ? 1 : 0);
    int rloc = lrow & 63;
    int nst = 2 * tt + 2;

    flash_load_kv(dynh, dynh + 4608, kb, vtb, 0, tid);

    for (int st = 0; st < nst; st++) {
        int s = st & 1;
        __half* Ks = dynh + s * 9216;
        __half* Vs = Ks + 4608;
        if (st + 1 < nst) {
            __half* Kn = dynh + (s ^ 1) * 9216;
            flash_load_kv(Kn, Kn + 4608, kb, vtb, (st + 1) * 64, tid);
            cp_wait<1>();
        } else {
            cp_wait<0>();
        }
        __syncthreads();

        // ---- scores = Q @ K^T (log2-domain: q pre-scaled by log2e)
        float sc[8][4] = {};
        #pragma unroll
        for (int kk = 0; kk < 4; kk++) {
            #pragma unroll
            for (int jb = 0; jb < 4; jb++) {
                unsigned rr[4];
                int n = jb * 16 + b_row;
                ldm_x4(rr, sptr(&Ks[n * 72 + kk * 16 + b_col]));
                mma16(sc[2 * jb],     qf[kk], rr);
                mma16(sc[2 * jb + 1], qf[kk], rr + 2);
            }
        }

        if (st >= 2 * tt) {
            int s0 = st * 64;
            int rg0 = t0 + lrow, rg1 = rg0 + 8;
            #pragma unroll
            for (int j = 0; j < 8; j++) {
                int cg = s0 + j * 8 + 2 * tig;
                if (cg     > rg0) sc[j][0] = -1e30f;
                if (cg + 1 > rg0) sc[j][1] = -1e30f;
                if (cg     > rg1) sc[j][2] = -1e30f;
                if (cg + 1 > rg1) sc[j][3] = -1e30f;
            }
        }

        float mx0 = -1e30f, mx1 = -1e30f;
        #pragma unroll
        for (int j = 0; j < 8; j++) {
            mx0 = fmaxf(mx0, fmaxf(sc[j][0], sc[j][1]));
            mx1 = fmaxf(mx1, fmaxf(sc[j][2], sc[j][3]));
        }
        mx0 = fmaxf(mx0, __shfl_xor_sync(0xffffffffu, mx0, 1));
        mx0 = fmaxf(mx0, __shfl_xor_sync(0xffffffffu, mx0, 2));
        mx1 = fmaxf(mx1, __shfl_xor_sync(0xffffffffu, mx1, 1));
        mx1 = fmaxf(mx1, __shfl_xor_sync(0xffffffffu, mx1, 2));

        float mn0 = fmaxf(m0v, mx0), mn1 = fmaxf(m1v, mx1);
        float fac0 = fast_exp2(m0v - mn0), fac1 = fast_exp2(m1v - mn1);

        float s0v = 0.0f, s1v = 0.0f;
        #pragma unroll
        for (int j = 0; j < 8; j++) {
            sc[j][0] = fast_exp2(sc[j][0] - mn0);
            sc[j][1] = fast_exp2(sc[j][1] - mn0);
            sc[j][2] = fast_exp2(sc[j][2] - mn1);
            sc[j][3] = fast_exp2(sc[j][3] - mn1);
            s0v += sc[j][0] + sc[j][1];
            s1v += sc[j][2] + sc[j][3];
        }
        s0v += __shfl_xor_sync(0xffffffffu, s0v, 1);
        s0v += __shfl_xor_sync(0xffffffffu, s0v, 2);
        s1v += __shfl_xor_sync(0xffffffffu, s1v, 1);
        s1v += __shfl_xor_sync(0xffffffffu, s1v, 2);

        l0 = l0 * fac0 + s0v;
        l1 = l1 * fac1 + s1v;
        m0v = mn0; m1v = mn1;

        #pragma unroll
        for (int j = 0; j < 8; j++) {
            acc_o[j][0] *= fac0; acc_o[j][1] *= fac0;
            acc_o[j][2] *= fac1; acc_o[j][3] *= fac1;
        }

        unsigned p0[8], p1[8];
        #pragma unroll
        for (int j = 0; j < 8; j++) {
            __half2 a = __floats2half2_rn(sc[j][0], sc[j][1]);
            __half2 b2 = __floats2half2_rn(sc[j][2], sc[j][3]);
            p0[j] = *(unsigned*)&a;
            p1[j] = *(unsigned*)&b2;
        }

        __half* tb = g_e + ((size_t)(bh * NT + tt64) * NT + st) * 4096;
        #pragma unroll
        for (int j = 0; j < 8; j++) {
            int c = j * 8 + 2 * tig;
            *(unsigned*)(tb + rloc * 64 + c)       = p0[j];
            *(unsigned*)(tb + (rloc + 8) * 64 + c) = p1[j];
        }
        if (tig == 0) {
            g_mloc[((size_t)bh * T_ + t0 + lrow) * NT + st]     = mn0;
            g_mloc[((size_t)bh * T_ + t0 + lrow + 8) * NT + st] = mn1;
        }

        #pragma unroll
        for (int kk = 0; kk < 4; kk++) {
            unsigned af[4] = { p0[2 * kk], p1[2 * kk], p0[2 * kk + 1], p1[2 * kk + 1] };
            #pragma unroll
            for (int jb = 0; jb < 4; jb++) {
                unsigned rr[4];
                int n = jb * 16 + b_row;
                ldm_x4(rr, sptr(&Vs[n * 72 + kk * 16 + b_col]));
                mma16(acc_o[2 * jb],     af, rr);
                mma16(acc_o[2 * jb + 1], af, rr + 2);
            }
        }
        __syncthreads();
    }

    int b = bh >> 4, h = bh & 15;
    float inv0 = 1.0f / l0, inv1 = 1.0f / l1;
    #pragma unroll
    for (int j = 0; j < 8; j++) {
        int d = h * 64 + j * 8 + 2 * tig;
        __half2 h0 = __floats2half2_rn(acc_o[j][0] * inv0, acc_o[j][1] * inv0);
        __half2 h1 = __floats2half2_rn(acc_o[j][2] * inv1, acc_o[j][3] * inv1);
        *(__half2*)&g_attn[((size_t)(t0 + lrow) * B_ + b) * D_ + d] = h0;
        *(__half2*)&g_attn[((size_t)(t0 + lrow + 8) * B_ + b) * D_ + d] = h1;
    }
    if (tig == 0) {
        g_lse[(size_t)bh * T_ + t0 + lrow]     = m0v + log2f(l0);
        g_lse[(size_t)bh * T_ + t0 + lrow + 8] = m1v + log2f(l1);
    }
}

// ---------------------------------------------------------------------------
// Avg weights: precompute all 16 heads' scale factors once, then stream
// the h-loop sync-free with deep unroll (MLP).
// ---------------------------------------------------------------------------
__global__ __launch_bounds__(256) void avg_kernel(float* __restrict__ out)
{
    __shared__ float sfac[16][64];
    int st = blockIdx.x, tt = blockIdx.y, b = blockIdx.z;
    int t0 = tt * 64, s0 = st * 64;
    int tid = threadIdx.x;
    int row = tid >> 2, cseg = (tid & 3) * 16;

    float* dst = out + (size_t)ROWS * D_ + (size_t)b * T_ * T_;
    float4* pout = (float4*)(dst + (size_t)(t0 + row) * T_ + s0 + cseg);

    if (st > tt) {
        float4 z = {0.f, 0.f, 0.f, 0.f};
        pout[0] = z; pout[1] = z; pout[2] = z; pout[3] = z;
        return;
    }

    // precompute sfac[h][r] = 2^(mloc - lse) for all 16 heads (one sync)
    #pragma unroll
    for (int q = 0; q < 4; q++) {
        int idx = tid * 4 + q;
        int h = idx >> 6, r = idx & 63;
        size_t rowg = (size_t)(b * H_ + h) * T_ + t0 + r;
        sfac[h][r] = fast_exp2(g_mloc[rowg * NT + st] - g_lse[rowg]);
    }
    __syncthreads();

    float acc[16] = {};
    const __half* ebase = g_e + ((size_t)(b * H_) * NT + tt) * NT * 4096
                          + (size_t)st * 4096 + row * 64 + cseg;
    #pragma unroll 4
    for (int h = 0; h < H_; h++) {
        float fac = sfac[h][row];
        const uint4* ep = (const uint4*)(ebase + (size_t)h * NT * NT * 4096);
        #pragma unroll
        for (int q2 = 0; q2 < 2; q2++) {
            uint4 u = ep[q2];
            const __half2* hp = (const __half2*)&u;
            #pragma unroll
            for (int i = 0; i < 4; i++) {
                float2 f = __half22float2(hp[i]);
                acc[q2 * 8 + i * 2]     += fac * f.x;
                acc[q2 * 8 + i * 2 + 1] += fac * f.y;
            }
        }
    }
    const float invH = 1.0f / (float)H_;
    #pragma unroll
    for (int q2 = 0; q2 < 4; q2++) {
        float4 v = { acc[q2 * 4] * invH, acc[q2 * 4 + 1] * invH,
                     acc[q2 * 4 + 2] * invH, acc[q2 * 4 + 3] * invH };
        pout[q2] = v;
    }
}

// ---------------------------------------------------------------------------
extern "C" void kernel_launch(void* const* d_in, const int* in_sizes, int n_in,
                              void* d_out, int out_size)
{
    const float* query = (const float*)d_in[0];
    const float* qw = (const float*)d_in[1];
    const float* qb = (const float*)d_in[2];
    const float* kw = (const float*)d_in[3];
    const float* kb = (const float*)d_in[4];
    const float* vw = (const float*)d_in[5];
    const float* vb = (const float*)d_in[6];
    const float* ow = (const float*)d_in[7];
    const float* ob = (const float*)d_in[8];
    float* out = (float*)d_out;

    const int SM_G = 73728;   // gemm: 2 stages x (A+W), BK=64
    const int SM_F = 36864;   // flash
    cudaFuncSetAttribute(gemm_fp16, cudaFuncAttributeMaxDynamicSharedMemorySize, SM_G);
    cudaFuncSetAttribute(flash_fp16, cudaFuncAttributeMaxDynamicSharedMemorySize, SM_F);

    prep_half<<<8192, 256>>>(query, qw, kw, vw, ow);
    gemm_fp16<<<dim3(8, 32, 3), 256, SM_G>>>(qb, kb, vb, nullptr, -1);
    flash_fp16<<<dim3(NQT, BH), 256, SM_F>>>();
    avg_kernel<<<dim3(NT, NT, B_), 256>>>(out);
    gemm_fp16<<<dim3(8, 32, 1), 256, SM_G>>>(ob, ob, ob, out, 3);
}

// round 9
// speedup vs baseline: 6.9138x; 1.0182x over previous
#include <cuda_runtime.h>
#include <cuda_fp16.h>
#include <math.h>
#include <stdint.h>

#define T_  2048
#define B_  2
#define D_  1024
#define H_  16
#define HD  64
#define ROWS (T_*B_)   // 4096
#define BH  (B_*H_)    // 32
#define NT  (T_/64)    // 32 (64-col score tiles)
#define NQT (T_/128)   // 16 (128-row q blocks)
#define SCALING 0.125f
#define QSCALE  (0.125f * 1.4426950408889634f)   // fold log2(e) into q

// ---------------- scratch (static device globals) ---------------------------
__device__ __half g_x [ROWS * D_];
__device__ __half g_wq[D_ * D_], g_wk[D_ * D_], g_wv[D_ * D_], g_wo[D_ * D_];
__device__ __half g_qh[BH * T_ * HD];          // [bh][t][d]  (q pre-scaled by QSCALE)
__device__ __half g_kh[BH * T_ * HD];          // [bh][t][d]
__device__ __half g_vt[BH * HD * T_];          // [bh][d][t]
__device__ __half g_attn[ROWS * D_];
__device__ float  g_lse [BH * T_];             // base-2 lse
__device__ float  g_mloc[BH * T_ * NT];        // base-2 running max per s-tile
__device__ __half g_e[(size_t)BH * T_ * T_];

// ---------------- helpers ---------------------------------------------------
__device__ __forceinline__ uint32_t sptr(const void* p) {
    return (uint32_t)__cvta_generic_to_shared(p);
}

__device__ __forceinline__ void cp16(const void* dst_smem, const void* src) {
    uint32_t d = (uint32_t)__cvta_generic_to_shared(dst_smem);
    asm volatile("cp.async.cg.shared.global [%0], [%1], 16;" :: "r"(d), "l"(src));
}
#define CP_COMMIT() asm volatile("cp.async.commit_group;")
template<int N> __device__ __forceinline__ void cp_wait() {
    asm volatile("cp.async.wait_group %0;" :: "n"(N));
}

__device__ __forceinline__ void mma16(float c[4], const unsigned a[4], const unsigned b[2]) {
    asm volatile(
        "mma.sync.aligned.m16n8k16.row.col.f32.f16.f16.f32 "
        "{%0,%1,%2,%3},{%4,%5,%6,%7},{%8,%9},{%0,%1,%2,%3};"
        : "+f"(c[0]), "+f"(c[1]), "+f"(c[2]), "+f"(c[3])
        : "r"(a[0]), "r"(a[1]), "r"(a[2]), "r"(a[3]), "r"(b[0]), "r"(b[1]));
}

__device__ __forceinline__ void ldm_x4(unsigned r[4], uint32_t addr) {
    asm volatile("ldmatrix.sync.aligned.m8n8.x4.shared.b16 {%0,%1,%2,%3}, [%4];"
        : "=r"(r[0]), "=r"(r[1]), "=r"(r[2]), "=r"(r[3]) : "r"(addr));
}

// 2^x for x <= ~0, FMA-pipe only (no MUFU). Input already in log2 domain.
__device__ __forceinline__ float fast_exp2(float x) {
    x = fmaxf(x, -100.0f);
    float t = x + 12582912.0f;                  // round-to-nearest-int magic
    int   i = __float_as_int(t) - 0x4B400000;
    float f = x - (t - 12582912.0f);            // f in [-0.5, 0.5]
    float p = 1.3333558146e-3f;
    p = fmaf(p, f, 9.6181291076e-3f);
    p = fmaf(p, f, 5.5504108664e-2f);
    p = fmaf(p, f, 2.4022650696e-1f);
    p = fmaf(p, f, 6.9314718056e-1f);
    p = fmaf(p, f, 1.0f);
    return __int_as_float(__float_as_int(p) + (i << 23));
}

// ---------------------------------------------------------------------------
// Prep: fp16-convert query + weights.
// ---------------------------------------------------------------------------
__global__ __launch_bounds__(256) void prep_half(
    const float* __restrict__ q,  const float* __restrict__ wq,
    const float* __restrict__ wk, const float* __restrict__ wv,
    const float* __restrict__ wo)
{
    const size_t NX = (size_t)ROWS * D_ / 4;
    const size_t NW = (size_t)D_ * D_ / 4;
    size_t i = (size_t)blockIdx.x * 256 + threadIdx.x;
    const float* src; __half* dst; size_t off;
    if      (i < NX)        { src = q;  dst = g_x;  off = i; }
    else if (i < NX + NW)   { src = wq; dst = g_wq; off = i - NX; }
    else if (i < NX + 2*NW) { src = wk; dst = g_wk; off = i - NX - NW; }
    else if (i < NX + 3*NW) { src = wv; dst = g_wv; off = i - NX - 2*NW; }
    else                    { src = wo; dst = g_wo; off = i - NX - 3*NW; }
    float4 v = ((const float4*)src)[off];
    __half2 h0 = __floats2half2_rn(v.x, v.y);
    __half2 h1 = __floats2half2_rn(v.z, v.w);
    uint2 u = { *(unsigned*)&h0, *(unsigned*)&h1 };
    ((uint2*)dst)[off] = u;
}

// ---------------------------------------------------------------------------
// GEMM (fp16 m16n8k16 + ldmatrix, cp.async 2-stage, BK=64, 2 CTAs/SM).
// ---------------------------------------------------------------------------
extern __shared__ __half dynh[];

__device__ __forceinline__ void gemm_load_stage(
    __half* buf, const __half* Ain, const __half* W,
    int m0, int n0, int k0, int tid)
{
    #pragma unroll
    for (int p = 0; p < 8; p++) {
        int i = p * 256 + tid;            // 0..2047 chunks of 8 halfs
        int which = i >> 10;              // 0 = A, 1 = W
        int j = i & 1023;
        int row = j >> 3, c = (j & 7) * 8;
        const __half* src = which
            ? (W   + (size_t)(n0 + row) * D_ + k0 + c)
            : (Ain + (size_t)(m0 + row) * D_ + k0 + c);
        cp16(buf + which * 9216 + row * 72 + c, src);
    }
    CP_COMMIT();
}

__global__ __launch_bounds__(256, 2) void gemm_fp16(
    const float* __restrict__ Bi0, const float* __restrict__ Bi1,
    const float* __restrict__ Bi2, float* __restrict__ C, int modeSel)
{
    int mode = (modeSel < 0) ? (int)blockIdx.z : modeSel;
    const __half* W    = (mode == 1) ? g_wk : (mode == 2) ? g_wv : (mode == 3) ? g_wo : g_wq;
    const float* bias  = (mode == 1) ? Bi1 : (mode == 2) ? Bi2 : Bi0;
    const __half* Ain  = (mode == 3) ? g_attn : g_x;

    int m0 = blockIdx.y * 128;
    int n0 = blockIdx.x * 128;
    int tid = threadIdx.x, lane = tid & 31, warp = tid >> 5;
    int mw = warp >> 1, nw = warp & 1;
    int gid = lane >> 2, tig = lane & 3;

    int a_row = lane & 15;
    int a_col = ((lane >> 4) & 1) * 8;
    int b_row = ((lane >> 4) & 1) * 8 + (lane & 7);
    int b_col = ((lane >> 3) & 1) * 8;

    float acc[2][8][4] = {};

    gemm_load_stage(dynh, Ain, W, m0, n0, 0, tid);

    for (int kt = 0; kt < 16; kt++) {            // BK = 64
        int s = kt & 1;
        __half* AsS = dynh + s * 18432;
        __half* WsS = AsS + 9216;
        if (kt + 1 < 16) {
            gemm_load_stage(dynh + (s ^ 1) * 18432, Ain, W, m0, n0, (kt + 1) * 64, tid);
            cp_wait<1>();
        } else {
            cp_wait<0>();
        }
        __syncthreads();

        #pragma unroll
        for (int kc = 0; kc < 4; kc++) {
            unsigned af[2][4];
            #pragma unroll
            for (int mi = 0; mi < 2; mi++) {
                int r = mw * 32 + mi * 16 + a_row;
                ldm_x4(af[mi], sptr(&AsS[r * 72 + kc * 16 + a_col]));
            }
            #pragma unroll
            for (int jb = 0; jb < 4; jb++) {
                unsigned rr[4];
                int n = nw * 64 + jb * 16 + b_row;
                ldm_x4(rr, sptr(&WsS[n * 72 + kc * 16 + b_col]));
                mma16(acc[0][2 * jb],     af[0], rr);
                mma16(acc[1][2 * jb],     af[1], rr);
                mma16(acc[0][2 * jb + 1], af[0], rr + 2);
                mma16(acc[1][2 * jb + 1], af[1], rr + 2);
            }
        }
        __syncthreads();
    }

    #pragma unroll
    for (int mi = 0; mi < 2; mi++) {
        int r = m0 + mw * 32 + mi * 16 + gid;
        #pragma unroll
        for (int j = 0; j < 8; j++) {
            int c = n0 + nw * 64 + j * 8 + tig * 2;
            float b0v = bias[c], b1v = bias[c + 1];
            float2 v0 = { acc[mi][j][0] + b0v, acc[mi][j][1] + b1v };
            float2 v1 = { acc[mi][j][2] + b0v, acc[mi][j][3] + b1v };
            if (mode == 0) { v0.x *= QSCALE; v0.y *= QSCALE; v1.x *= QSCALE; v1.y *= QSCALE; }
            if (mode == 3) {
                *(float2*)&C[(size_t)r * D_ + c] = v0;
                *(float2*)&C[(size_t)(r + 8) * D_ + c] = v1;
            } else if (mode == 2) {
                int h = c >> 6, d = c & 63;
                int t = r >> 1, b = r & 1;
                size_t base = ((size_t)(b * H_ + h) * HD + d) * T_;
                g_vt[base + t]      = __float2half(v0.x);
                g_vt[base + T_ + t] = __float2half(v0.y);
                int t8 = t + 4;
                g_vt[base + t8]      = __float2half(v1.x);
                g_vt[base + T_ + t8] = __float2half(v1.y);
            } else {
                __half* outp = (mode == 0) ? g_qh : g_kh;
                int h = c >> 6, d = c & 63;
                int t = r >> 1, b = r & 1;
                __half2 h0 = __floats2half2_rn(v0.x, v0.y);
                __half2 h1 = __floats2half2_rn(v1.x, v1.y);
                *(__half2*)&outp[((size_t)(b * H_ + h) * T_ + t) * HD + d] = h0;
                *(__half2*)&outp[((size_t)(b * H_ + h) * T_ + t + 4) * HD + d] = h1;
            }
        }
    }
}

// ---------------------------------------------------------------------------
// Flash attention (fp16 m16n8k16 + ldmatrix, cp.async 2-stage, base-2 softmax).
// ---------------------------------------------------------------------------
__device__ __forceinline__ void flash_load_kv(
    __half* Kst, __half* Vst, const __half* kb, const __half* vtb, int s0, int tid)
{
    #pragma unroll
    for (int p = 0; p < 2; p++) {
        int i = p * 256 + tid;
        int row = i >> 3, c = (i & 7) * 8;
        cp16(Kst + row * 72 + c, kb  + (size_t)(s0 + row) * HD + c);
        cp16(Vst + row * 72 + c, vtb + (size_t)row * T_ + s0 + c);
    }
    CP_COMMIT();
}

__global__ __launch_bounds__(256) void flash_fp16()
{
    int bh = blockIdx.y;
    int tt = (int)(gridDim.x - 1 - blockIdx.x);
    int t0 = tt * 128;
    int tid = threadIdx.x, lane = tid & 31, w = tid >> 5;
    int gid = lane >> 2, tig = lane & 3;
    int lrow = w * 16 + gid;

    int a_row = lane & 15;
    int a_col = ((lane >> 4) & 1) * 8;
    int b_row = ((lane >> 4) & 1) * 8 + (lane & 7);
    int b_col = ((lane >> 3) & 1) * 8;

    const __half* qb  = g_qh + (size_t)bh * T_ * HD;
    const __half* kb  = g_kh + (size_t)bh * T_ * HD;
    const __half* vtb = g_vt + (size_t)bh * HD * T_;

    {
        #pragma unroll
        for (int p = 0; p < 4; p++) {
            int i = p * 256 + tid;
            int row = i >> 3, c = (i & 7) * 8;
            uint4 v = *(const uint4*)(qb + (size_t)(t0 + row) * HD + c);
            *(uint4*)(dynh + row * 72 + c) = v;
        }
    }
    __syncthreads();
    unsigned qf[4][4];
    {
        int r = w * 16 + a_row;
        #pragma unroll
        for (int kk = 0; kk < 4; kk++)
            ldm_x4(qf[kk], sptr(&dynh[r * 72 + kk * 16 + a_col]));
    }
    __syncthreads();

    float acc_o[8][4] = {};
    float m0v = -1e30f, m1v = -1e30f, l0 = 0.0f, l1 = 0.0f;

    int tt64 = tt * 2 + (lrow >= 64 ? 1 : 0);
    int rloc = lrow & 63;
    int nst = 2 * tt + 2;

    flash_load_kv(dynh, dynh + 4608, kb, vtb, 0, tid);

    for (int st = 0; st < nst; st++) {
        int s = st & 1;
        __half* Ks = dynh + s * 9216;
        __half* Vs = Ks + 4608;
        if (st + 1 < nst) {
            __half* Kn = dynh + (s ^ 1) * 9216;
            flash_load_kv(Kn, Kn + 4608, kb, vtb, (st + 1) * 64, tid);
            cp_wait<1>();
        } else {
            cp_wait<0>();
        }
        __syncthreads();

        float sc[8][4] = {};
        #pragma unroll
        for (int kk = 0; kk < 4; kk++) {
            #pragma unroll
            for (int jb = 0; jb < 4; jb++) {
                unsigned rr[4];
                int n = jb * 16 + b_row;
                ldm_x4(rr, sptr(&Ks[n * 72 + kk * 16 + b_col]));
                mma16(sc[2 * jb],     qf[kk], rr);
                mma16(sc[2 * jb + 1], qf[kk], rr + 2);
            }
        }

        if (st >= 2 * tt) {
            int s0 = st * 64;
            int rg0 = t0 + lrow, rg1 = rg0 + 8;
            #pragma unroll
            for (int j = 0; j < 8; j++) {
                int cg = s0 + j * 8 + 2 * tig;
                if (cg     > rg0) sc[j][0] = -1e30f;
                if (cg + 1 > rg0) sc[j][1] = -1e30f;
                if (cg     > rg1) sc[j][2] = -1e30f;
                if (cg + 1 > rg1) sc[j][3] = -1e30f;
            }
        }

        float mx0 = -1e30f, mx1 = -1e30f;
        #pragma unroll
        for (int j = 0; j < 8; j++) {
            mx0 = fmaxf(mx0, fmaxf(sc[j][0], sc[j][1]));
            mx1 = fmaxf(mx1, fmaxf(sc[j][2], sc[j][3]));
        }
        mx0 = fmaxf(mx0, __shfl_xor_sync(0xffffffffu, mx0, 1));
        mx0 = fmaxf(mx0, __shfl_xor_sync(0xffffffffu, mx0, 2));
        mx1 = fmaxf(mx1, __shfl_xor_sync(0xffffffffu, mx1, 1));
        mx1 = fmaxf(mx1, __shfl_xor_sync(0xffffffffu, mx1, 2));

        float mn0 = fmaxf(m0v, mx0), mn1 = fmaxf(m1v, mx1);
        float fac0 = fast_exp2(m0v - mn0), fac1 = fast_exp2(m1v - mn1);

        float s0v = 0.0f, s1v = 0.0f;
        #pragma unroll
        for (int j = 0; j < 8; j++) {
            sc[j][0] = fast_exp2(sc[j][0] - mn0);
            sc[j][1] = fast_exp2(sc[j][1] - mn0);
            sc[j][2] = fast_exp2(sc[j][2] - mn1);
            sc[j][3] = fast_exp2(sc[j][3] - mn1);
            s0v += sc[j][0] + sc[j][1];
            s1v += sc[j][2] + sc[j][3];
        }
        s0v += __shfl_xor_sync(0xffffffffu, s0v, 1);
        s0v += __shfl_xor_sync(0xffffffffu, s0v, 2);
        s1v += __shfl_xor_sync(0xffffffffu, s1v, 1);
        s1v += __shfl_xor_sync(0xffffffffu, s1v, 2);

        l0 = l0 * fac0 + s0v;
        l1 = l1 * fac1 + s1v;
        m0v = mn0; m1v = mn1;

        #pragma unroll
        for (int j = 0; j < 8; j++) {
            acc_o[j][0] *= fac0; acc_o[j][1] *= fac0;
            acc_o[j][2] *= fac1; acc_o[j][3] *= fac1;
        }

        unsigned p0[8], p1[8];
        #pragma unroll
        for (int j = 0; j < 8; j++) {
            __half2 a = __floats2half2_rn(sc[j][0], sc[j][1]);
            __half2 b2 = __floats2half2_rn(sc[j][2], sc[j][3]);
            p0[j] = *(unsigned*)&a;
            p1[j] = *(unsigned*)&b2;
        }

        __half* tb = g_e + ((size_t)(bh * NT + tt64) * NT + st) * 4096;
        #pragma unroll
        for (int j = 0; j < 8; j++) {
            int c = j * 8 + 2 * tig;
            *(unsigned*)(tb + rloc * 64 + c)       = p0[j];
            *(unsigned*)(tb + (rloc + 8) * 64 + c) = p1[j];
        }
        if (tig == 0) {
            g_mloc[((size_t)bh * T_ + t0 + lrow) * NT + st]     = mn0;
            g_mloc[((size_t)bh * T_ + t0 + lrow + 8) * NT + st] = mn1;
        }

        #pragma unroll
        for (int kk = 0; kk < 4; kk++) {
            unsigned af[4] = { p0[2 * kk], p1[2 * kk], p0[2 * kk + 1], p1[2 * kk + 1] };
            #pragma unroll
            for (int jb = 0; jb < 4; jb++) {
                unsigned rr[4];
                int n = jb * 16 + b_row;
                ldm_x4(rr, sptr(&Vs[n * 72 + kk * 16 + b_col]));
                mma16(acc_o[2 * jb],     af, rr);
                mma16(acc_o[2 * jb + 1], af, rr + 2);
            }
        }
        __syncthreads();
    }

    int b = bh >> 4, h = bh & 15;
    float inv0 = 1.0f / l0, inv1 = 1.0f / l1;
    #pragma unroll
    for (int j = 0; j < 8; j++) {
        int d = h * 64 + j * 8 + 2 * tig;
        __half2 h0 = __floats2half2_rn(acc_o[j][0] * inv0, acc_o[j][1] * inv0);
        __half2 h1 = __floats2half2_rn(acc_o[j][2] * inv1, acc_o[j][3] * inv1);
        *(__half2*)&g_attn[((size_t)(t0 + lrow) * B_ + b) * D_ + d] = h0;
        *(__half2*)&g_attn[((size_t)(t0 + lrow + 8) * B_ + b) * D_ + d] = h1;
    }
    if (tig == 0) {
        g_lse[(size_t)bh * T_ + t0 + lrow]     = m0v + log2f(l0);
        g_lse[(size_t)bh * T_ + t0 + lrow + 8] = m1v + log2f(l1);
    }
}

// ---------------------------------------------------------------------------
// Avg weights: one-sync sfac precompute, sync-free streamed h-loop.
// ---------------------------------------------------------------------------
__global__ __launch_bounds__(256) void avg_kernel(float* __restrict__ out)
{
    __shared__ float sfac[16][64];
    int st = blockIdx.x, tt = blockIdx.y, b = blockIdx.z;
    int t0 = tt * 64, s0 = st * 64;
    int tid = threadIdx.x;
    int row = tid >> 2, cseg = (tid & 3) * 16;

    float* dst = out + (size_t)ROWS * D_ + (size_t)b * T_ * T_;
    float4* pout = (float4*)(dst + (size_t)(t0 + row) * T_ + s0 + cseg);

    if (st > tt) {
        float4 z = {0.f, 0.f, 0.f, 0.f};
        pout[0] = z; pout[1] = z; pout[2] = z; pout[3] = z;
        return;
    }

    #pragma unroll
    for (int q = 0; q < 4; q++) {
        int idx = tid * 4 + q;
        int h = idx >> 6, r = idx & 63;
        size_t rowg = (size_t)(b * H_ + h) * T_ + t0 + r;
        sfac[h][r] = fast_exp2(g_mloc[rowg * NT + st] - g_lse[rowg]);
    }
    __syncthreads();

    float acc[16] = {};
    const __half* ebase = g_e + ((size_t)(b * H_) * NT + tt) * NT * 4096
                          + (size_t)st * 4096 + row * 64 + cseg;
    #pragma unroll 4
    for (int h = 0; h < H_; h++) {
        float fac = sfac[h][row];
        const uint4* ep = (const uint4*)(ebase + (size_t)h * NT * NT * 4096);
        #pragma unroll
        for (int q2 = 0; q2 < 2; q2++) {
            uint4 u = ep[q2];
            const __half2* hp = (const __half2*)&u;
            #pragma unroll
            for (int i = 0; i < 4; i++) {
                float2 f = __half22float2(hp[i]);
                acc[q2 * 8 + i * 2]     += fac * f.x;
                acc[q2 * 8 + i * 2 + 1] += fac * f.y;
            }
        }
    }
    const float invH = 1.0f / (float)H_;
    #pragma unroll
    for (int q2 = 0; q2 < 4; q2++) {
        float4 v = { acc[q2 * 4] * invH, acc[q2 * 4 + 1] * invH,
                     acc[q2 * 4 + 2] * invH, acc[q2 * 4 + 3] * invH };
        pout[q2] = v;
    }
}

// ---------------------------------------------------------------------------
extern "C" void kernel_launch(void* const* d_in, const int* in_sizes, int n_in,
                              void* d_out, int out_size)
{
    const float* query = (const float*)d_in[0];
    const float* qw = (const float*)d_in[1];
    const float* qb = (const float*)d_in[2];
    const float* kw = (const float*)d_in[3];
    const float* kb = (const float*)d_in[4];
    const float* vw = (const float*)d_in[5];
    const float* vb = (const float*)d_in[6];
    const float* ow = (const float*)d_in[7];
    const float* ob = (const float*)d_in[8];
    float* out = (float*)d_out;

    const int SM_G = 73728;
    const int SM_F = 36864;
    cudaFuncSetAttribute(gemm_fp16, cudaFuncAttributeMaxDynamicSharedMemorySize, SM_G);
    cudaFuncSetAttribute(flash_fp16, cudaFuncAttributeMaxDynamicSharedMemorySize, SM_F);

    // one-time side-stream + events for the avg || outproj fork (no device mem)
    static cudaStream_t s2 = nullptr;
    static cudaEvent_t evFork = nullptr, evJoin = nullptr;
    static bool init_ok = false;
    static bool init_tried = false;
    if (!init_tried) {
        init_tried = true;
        init_ok = (cudaStreamCreateWithFlags(&s2, cudaStreamNonBlocking) == cudaSuccess)
               && (cudaEventCreateWithFlags(&evFork, cudaEventDisableTiming) == cudaSuccess)
               && (cudaEventCreateWithFlags(&evJoin, cudaEventDisableTiming) == cudaSuccess);
    }

    prep_half<<<8192, 256>>>(query, qw, kw, vw, ow);
    gemm_fp16<<<dim3(8, 32, 3), 256, SM_G>>>(qb, kb, vb, nullptr, -1);
    flash_fp16<<<dim3(NQT, BH), 256, SM_F>>>();

    if (init_ok) {
        // fork: avg on s2, outproj on main stream, then join
        cudaEventRecord(evFork, 0);
        cudaStreamWaitEvent(s2, evFork, 0);
        avg_kernel<<<dim3(NT, NT, B_), 256, 0, s2>>>(out);
        gemm_fp16<<<dim3(8, 32, 1), 256, SM_G>>>(ob, ob, ob, out, 3);
        cudaEventRecord(evJoin, s2);
        cudaStreamWaitEvent(0, evJoin, 0);
    } else {
        avg_kernel<<<dim3(NT, NT, B_), 256>>>(out);
        gemm_fp16<<<dim3(8, 32, 1), 256, SM_G>>>(ob, ob, ob, out, 3);
    }
}